// round 13
// baseline (speedup 1.0000x reference)
#include <cuda_runtime.h>
#include <cuda_bf16.h>
#include <cstdint>
#include <cstring>

typedef unsigned long long ull;

// Problem constants
#define BATCH 8
#define CHAN  256
#define HEADS 8
#define DHEAD 32
#define NTOK  1024
#define NPER  262144
#define BIASN 3969

// ---------------- scratch ----------------
// W fragments: [p][tap][split][kc(16)][npair(16)][lane(32)][2 frag x 8B]
__device__ __align__(16) __nv_bfloat16 g_wfragB[3*9*2*16*32*32*4];
// X transposed+padded bf16 split: [b][split][y(34)][x(34)][c(256)]
__device__ __align__(16) __nv_bfloat16 g_xbfT[8*2*34*34*256];
__device__ __align__(16) float g_woT[256*256];                 // [c][o]
__device__ __align__(16) float g_act[3][BATCH*NPER];           // conv->gelu activations
__device__ __align__(16) float g_part[3][BATCH][16][2];        // GN partials (16 ntiles)
__device__ __align__(16) float g_attn[BATCH*NPER];

// ---------------- f32x2 helpers ----------------
__device__ __forceinline__ void ffma2(ull& d, ull a, ull b) {
    asm("fma.rn.f32x2 %0, %1, %2, %0;" : "+l"(d) : "l"(a), "l"(b));
}
__device__ __forceinline__ ull pack2(float a, float b) {
    ull u; asm("mov.b64 %0, {%1,%2};" : "=l"(u) : "f"(a), "f"(b)); return u;
}
__device__ __forceinline__ float lo2(ull u) { return __int_as_float((int)(unsigned)u); }
__device__ __forceinline__ float hi2(ull u) { return __int_as_float((int)(u >> 32)); }

// ---------------- warp mma helper (bf16, fp32 accum) ----------------
__device__ __forceinline__ void mma16816(float* c, const uint32_t* a, const uint32_t* b) {
    asm volatile("mma.sync.aligned.m16n8k16.row.col.f32.bf16.bf16.f32 "
        "{%0,%1,%2,%3}, {%4,%5,%6,%7}, {%8,%9}, {%0,%1,%2,%3};"
        : "+f"(c[0]), "+f"(c[1]), "+f"(c[2]), "+f"(c[3])
        : "r"(a[0]), "r"(a[1]), "r"(a[2]), "r"(a[3]), "r"(b[0]), "r"(b[1]));
}

// split two f32 into bf16x2 hi-word and lo-word
__device__ __forceinline__ void split2(float v0, float v1, uint32_t& hi, uint32_t& lo) {
    __nv_bfloat16 h0 = __float2bfloat16(v0), h1 = __float2bfloat16(v1);
    __nv_bfloat16 l0 = __float2bfloat16(v0 - __bfloat162float(h0));
    __nv_bfloat16 l1 = __float2bfloat16(v1 - __bfloat162float(h1));
    __nv_bfloat162 ph; ph.x = h0; ph.y = h1;
    __nv_bfloat162 pl; pl.x = l0; pl.y = l1;
    hi = *reinterpret_cast<uint32_t*>(&ph);
    lo = *reinterpret_cast<uint32_t*>(&pl);
}

// ---------------- 1a) weight prep, ic-permuted fragment order ----------------
__global__ void prep_w_kernel(const float* __restrict__ wq,
                              const float* __restrict__ wk,
                              const float* __restrict__ wv) {
    const int sub = threadIdx.x >> 5, lane = threadIdx.x & 31;
    const int fi = blockIdx.x * 8 + sub;
    const int kc = fi >> 5, ntile = fi & 31;
    const int tap = blockIdx.y, p = blockIdx.z;
    const float* w = (p == 0) ? wq : (p == 1) ? wk : wv;
    const int t = lane & 3, g = lane >> 2;
    const int oc = ntile * 8 + g;
    const int k0 = kc * 16 + t * 4;
    const int npair = ntile >> 1, half = ntile & 1;

    float v0 = w[oc * 2304 + (k0    ) * 9 + tap];
    float v1 = w[oc * 2304 + (k0 + 1) * 9 + tap];
    float v2 = w[oc * 2304 + (k0 + 2) * 9 + tap];
    float v3 = w[oc * 2304 + (k0 + 3) * 9 + tap];

    __nv_bfloat16 h0 = __float2bfloat16(v0), h1 = __float2bfloat16(v1);
    __nv_bfloat16 h2 = __float2bfloat16(v2), h3 = __float2bfloat16(v3);
    __nv_bfloat16 l0 = __float2bfloat16(v0 - __bfloat162float(h0));
    __nv_bfloat16 l1 = __float2bfloat16(v1 - __bfloat162float(h1));
    __nv_bfloat16 l2 = __float2bfloat16(v2 - __bfloat162float(h2));
    __nv_bfloat16 l3 = __float2bfloat16(v3 - __bfloat162float(h3));

    int slot = (((((p * 9 + tap) * 2 + 0) * 16 + kc) * 16 + npair) * 32 + lane) * 2 + half;
    __nv_bfloat16* dh = g_wfragB + slot * 4;
    dh[0] = h0; dh[1] = h1; dh[2] = h2; dh[3] = h3;
    __nv_bfloat16* dl = dh + 16 * 32 * 32 * 4;
    dl[0] = l0; dl[1] = l1; dl[2] = l2; dl[3] = l3;
}

// ---------------- 1b) input transpose + pad + bf16-split ----------------
__global__ void prep_x_kernel(const float* __restrict__ x) {
    const int y = blockIdx.x, b = blockIdx.y, c = threadIdx.x;
    __shared__ float s_t[256][33];
    const bool rowvalid = (y >= 1 && y <= 32);
    if (rowvalid) {
        const float* src = x + ((b * 256 + c) * 32 + (y - 1)) * 32;
#pragma unroll
        for (int i = 0; i < 8; i++) {
            float4 v = reinterpret_cast<const float4*>(src)[i];
            s_t[c][i * 4 + 0] = v.x; s_t[c][i * 4 + 1] = v.y;
            s_t[c][i * 4 + 2] = v.z; s_t[c][i * 4 + 3] = v.w;
        }
    }
    __syncthreads();
    for (int xx = 0; xx < 34; xx++) {
        float v = (rowvalid && xx >= 1 && xx <= 32) ? s_t[c][xx - 1] : 0.f;
        __nv_bfloat16 hi = __float2bfloat16(v);
        __nv_bfloat16 lo = __float2bfloat16(v - __bfloat162float(hi));
        int base = (((b * 2) * 34 + y) * 34 + xx) * 256 + c;
        g_xbfT[base]              = hi;
        g_xbfT[base + 34*34*256]  = lo;
    }
}

// ---------------- 1c) wo transpose ----------------
__global__ void transpose_wo_kernel(const float* __restrict__ wo) {
    __shared__ float tile[32][33];
    const int c0 = blockIdx.x * 32, o0 = blockIdx.y * 32;
#pragma unroll
    for (int i = 0; i < 4; i++)
        tile[threadIdx.y + i * 8][threadIdx.x] = wo[(o0 + threadIdx.y + i * 8) * 256 + c0 + threadIdx.x];
    __syncthreads();
#pragma unroll
    for (int i = 0; i < 4; i++)
        g_woT[(c0 + threadIdx.y + i * 8) * 256 + o0 + threadIdx.x] =
            tile[threadIdx.x][threadIdx.y + i * 8];
}

// ---------------- 2) conv via mma.sync, pointer-strength-reduced mainloop ----------
// grid (16 pxtiles, 3 p, 8 b), block 256 (8 warps = 2m x 4n)
__global__ void __launch_bounds__(256) conv_mma_kernel() {
    const int nt  = blockIdx.x;
    const int p   = blockIdx.y;
    const int b   = blockIdx.z;
    const int tid = threadIdx.x, warp = tid >> 5, lane = tid & 31;
    const int wm = warp & 1, wn = warp >> 1;
    const int g = lane >> 2, t = lane & 3;
    const int px_warp = nt * 64 + wm * 32;

    float acc[2][8][4];
#pragma unroll
    for (int mt = 0; mt < 2; mt++)
#pragma unroll
        for (int n8 = 0; n8 < 8; n8++)
#pragma unroll
            for (int r = 0; r < 4; r++) acc[mt][n8][r] = 0.f;

    const ulonglong2* wfrag16 = reinterpret_cast<const ulonglong2*>(g_wfragB);

    for (int tap = 0; tap < 9; tap++) {
        const int ky = tap / 3, kx = tap - ky * 3;

        // hoisted bases (invariant over kc)
        const __nv_bfloat16* aptr[2][2];
#pragma unroll
        for (int mt = 0; mt < 2; mt++) {
            const int px = px_warp + mt * 16 + g;
            const int y  = (px >> 5) + ky;
            const int x  = (px & 31) + kx;
#pragma unroll
            for (int sp = 0; sp < 2; sp++)
                aptr[mt][sp] = g_xbfT + (((b * 2 + sp) * 34 + y) * 34 + x) * 256 + t * 4;
        }
        const ulonglong2* bptr[2];
#pragma unroll
        for (int sp = 0; sp < 2; sp++)
            bptr[sp] = wfrag16 + ((((p * 9 + tap) * 2 + sp) * 16) * 16 + wn * 4) * 32 + lane;

        for (int kc = 0; kc < 16; kc++) {
            // A fragments: 2 LDG.64 per (mt,sp)
            uint32_t afr[2][2][4];
#pragma unroll
            for (int mt = 0; mt < 2; mt++)
#pragma unroll
                for (int sp = 0; sp < 2; sp++) {
                    ull v0 = *reinterpret_cast<const ull*>(aptr[mt][sp]);
                    ull v1 = *reinterpret_cast<const ull*>(aptr[mt][sp] + 2048);
                    afr[sp][mt][0] = (uint32_t)v0;
                    afr[sp][mt][2] = (uint32_t)(v0 >> 32);
                    afr[sp][mt][1] = (uint32_t)v1;
                    afr[sp][mt][3] = (uint32_t)(v1 >> 32);
                    aptr[mt][sp] += 16;
                }
            // B fragments: 4 LDG.128 per sp
            uint32_t bfr[2][8][2];
#pragma unroll
            for (int sp = 0; sp < 2; sp++) {
#pragma unroll
                for (int n4 = 0; n4 < 4; n4++) {
                    ulonglong2 v = bptr[sp][n4 * 32];
                    bfr[sp][2 * n4][0]     = (uint32_t)v.x;
                    bfr[sp][2 * n4][1]     = (uint32_t)(v.x >> 32);
                    bfr[sp][2 * n4 + 1][0] = (uint32_t)v.y;
                    bfr[sp][2 * n4 + 1][1] = (uint32_t)(v.y >> 32);
                }
                bptr[sp] += 512;   // 16 npair * 32 lanes
            }
            // 3 split combos
#pragma unroll
            for (int combo = 0; combo < 3; combo++) {
                const int ws = combo >> 1, xs = combo & 1;
#pragma unroll
                for (int mt = 0; mt < 2; mt++)
#pragma unroll
                    for (int n8 = 0; n8 < 8; n8++)
                        mma16816(acc[mt][n8], afr[xs][mt], bfr[ws][n8]);
            }
        }
    }

    float s = 0.f, sq = 0.f;
#pragma unroll
    for (int mt = 0; mt < 2; mt++)
#pragma unroll
        for (int n8 = 0; n8 < 8; n8++)
#pragma unroll
            for (int r = 0; r < 4; r++) {
                float v  = acc[mt][n8][r];
                int   px = px_warp + mt * 16 + g + ((r >> 1) << 3);
                int   oc = wn * 64 + n8 * 8 + t * 2 + (r & 1);
                g_act[p][(b * 256 + oc) * 1024 + px] = v;
                s += v; sq += v * v;
            }
    __shared__ float red[512];
    red[tid] = s; red[tid + 256] = sq;
    __syncthreads();
    for (int st = 128; st > 0; st >>= 1) {
        if (tid < st) { red[tid] += red[tid + st]; red[tid + 256] += red[tid + 256 + st]; }
        __syncthreads();
    }
    if (tid == 0) {
        g_part[p][b][nt][0] = red[0];
        g_part[p][b][nt][1] = red[256];
    }
}

// ---------------- 3) GroupNorm(1) + exact GELU ----------------
__global__ void gn_gelu_kernel(const float* __restrict__ gq, const float* __restrict__ bq,
                               const float* __restrict__ gk, const float* __restrict__ bk,
                               const float* __restrict__ gv, const float* __restrict__ bv) {
    const int chunk = blockIdx.x;
    const int b     = blockIdx.y;
    const int p     = blockIdx.z;
    const float* gg = (p == 0) ? gq : (p == 1) ? gk : gv;
    const float* bb = (p == 0) ? bq : (p == 1) ? bk : bv;

    __shared__ float s_mu, s_rs;
    if (threadIdx.x < 16) {
        float s  = g_part[p][b][threadIdx.x][0];
        float sq = g_part[p][b][threadIdx.x][1];
#pragma unroll
        for (int o = 8; o > 0; o >>= 1) {
            s  += __shfl_down_sync(0x0000ffffu, s,  o);
            sq += __shfl_down_sync(0x0000ffffu, sq, o);
        }
        if (threadIdx.x == 0) {
            float mu  = s / (float)NPER;
            float var = sq / (float)NPER - mu * mu;
            s_mu = mu;
            s_rs = rsqrtf(var + 1e-6f);
        }
    }
    __syncthreads();
    const float mu = s_mu, rs = s_rs;

    float* base = &g_act[p][b * NPER + chunk * 32768];
    for (int i = threadIdx.x; i < 8192; i += 256) {
        float4 v = reinterpret_cast<float4*>(base)[i];
        int c = (chunk * 32768 + i * 4) >> 10;
        float gc = gg[c], bc = bb[c];
        float t0 = (v.x - mu) * rs * gc + bc;
        float t1 = (v.y - mu) * rs * gc + bc;
        float t2 = (v.z - mu) * rs * gc + bc;
        float t3 = (v.w - mu) * rs * gc + bc;
        v.x = 0.5f * t0 * (1.0f + erff(t0 * 0.70710678118654752f));
        v.y = 0.5f * t1 * (1.0f + erff(t1 * 0.70710678118654752f));
        v.z = 0.5f * t2 * (1.0f + erff(t2 * 0.70710678118654752f));
        v.w = 0.5f * t3 * (1.0f + erff(t3 * 0.70710678118654752f));
        reinterpret_cast<float4*>(base)[i] = v;
    }
}

// ---------------- 4) tensor-core flash attention (R12 version) ----------------
__global__ void __launch_bounds__(128) attn_kernel(const float* __restrict__ bias_table) {
    const int qt = blockIdx.x, h = blockIdx.y, b = blockIdx.z;
    const int tid = threadIdx.x, warp = tid >> 5, lane = tid & 31;
    const int g = lane >> 2, t = lane & 3;
    const int qw0 = qt * 128 + warp * 32;

    __shared__ float    s_bias[BIASN + 3];
    __shared__ uint32_t sK[2][32][17];
    __shared__ uint32_t sV[2][32][17];

    for (int i = tid; i < BIASN; i += 128)
        s_bias[i] = bias_table[i * HEADS + h];

    const float* aq = &g_act[0][(b * 256 + h * DHEAD) * NTOK];
    const float* ak = &g_act[1][(b * 256 + h * DHEAD) * NTOK];
    const float* av = &g_act[2][(b * 256 + h * DHEAD) * NTOK];

    uint32_t qf[2][2][2][4];
#pragma unroll
    for (int mt = 0; mt < 2; mt++) {
        const int row0 = qw0 + mt * 16 + g;
#pragma unroll
        for (int kc = 0; kc < 2; kc++) {
            const int kd = kc * 16;
            float a00 = aq[(kd + 2 * t    ) * NTOK + row0];
            float a01 = aq[(kd + 2 * t + 1) * NTOK + row0];
            float a10 = aq[(kd + 2 * t    ) * NTOK + row0 + 8];
            float a11 = aq[(kd + 2 * t + 1) * NTOK + row0 + 8];
            float a20 = aq[(kd + 8 + 2 * t    ) * NTOK + row0];
            float a21 = aq[(kd + 8 + 2 * t + 1) * NTOK + row0];
            float a30 = aq[(kd + 8 + 2 * t    ) * NTOK + row0 + 8];
            float a31 = aq[(kd + 8 + 2 * t + 1) * NTOK + row0 + 8];
            split2(a00, a01, qf[0][mt][kc][0], qf[1][mt][kc][0]);
            split2(a10, a11, qf[0][mt][kc][1], qf[1][mt][kc][1]);
            split2(a20, a21, qf[0][mt][kc][2], qf[1][mt][kc][2]);
            split2(a30, a31, qf[0][mt][kc][3], qf[1][mt][kc][3]);
        }
    }

    int yq[2][2], xq[2][2];
#pragma unroll
    for (int mt = 0; mt < 2; mt++)
#pragma unroll
        for (int rh = 0; rh < 2; rh++) {
            int q = qw0 + mt * 16 + g + rh * 8;
            yq[mt][rh] = q >> 5; xq[mt][rh] = q & 31;
        }

    float m[2][2], l[2][2];
    float o[2][4][4];
#pragma unroll
    for (int mt = 0; mt < 2; mt++)
#pragma unroll
        for (int rh = 0; rh < 2; rh++) { m[mt][rh] = -1e30f; l[mt][rh] = 0.f; }
#pragma unroll
    for (int mt = 0; mt < 2; mt++)
#pragma unroll
        for (int n = 0; n < 4; n++)
#pragma unroll
            for (int r = 0; r < 4; r++) o[mt][n][r] = 0.f;

    for (int kt = 0; kt < 32; kt++) {
        const int kv0 = kt * 32;
        __syncthreads();
        for (int e = tid; e < 512; e += 128) {
            int kv = e & 31, dp = e >> 5;
            float f0 = ak[(2 * dp)     * NTOK + kv0 + kv];
            float f1 = ak[(2 * dp + 1) * NTOK + kv0 + kv];
            uint32_t hi, lo;
            split2(f0, f1, hi, lo);
            sK[0][kv][dp] = hi; sK[1][kv][dp] = lo;
        }
        for (int e = tid; e < 512; e += 128) {
            int kvp = e & 15, d = e >> 4;
            float2 vv = *reinterpret_cast<const float2*>(&av[d * NTOK + kv0 + 2 * kvp]);
            uint32_t hi, lo;
            split2(vv.x, vv.y, hi, lo);
            sV[0][d][kvp] = hi; sV[1][d][kvp] = lo;
        }
        __syncthreads();

        float sc[2][4][4];
#pragma unroll
        for (int mt = 0; mt < 2; mt++)
#pragma unroll
            for (int j = 0; j < 4; j++)
#pragma unroll
                for (int r = 0; r < 4; r++) sc[mt][j][r] = 0.f;

#pragma unroll
        for (int kc = 0; kc < 2; kc++) {
            uint32_t kf[2][4][2];
#pragma unroll
            for (int sp = 0; sp < 2; sp++)
#pragma unroll
                for (int j = 0; j < 4; j++) {
                    kf[sp][j][0] = sK[sp][j * 8 + g][kc * 8 + t];
                    kf[sp][j][1] = sK[sp][j * 8 + g][kc * 8 + 4 + t];
                }
#pragma unroll
            for (int mt = 0; mt < 2; mt++)
#pragma unroll
                for (int j = 0; j < 4; j++) {
                    mma16816(sc[mt][j], qf[0][mt][kc], kf[0][j]);
                    mma16816(sc[mt][j], qf[1][mt][kc], kf[0][j]);
                    mma16816(sc[mt][j], qf[0][mt][kc], kf[1][j]);
                }
        }

#pragma unroll
        for (int mt = 0; mt < 2; mt++)
#pragma unroll
            for (int j = 0; j < 4; j++)
#pragma unroll
                for (int r = 0; r < 4; r++) {
                    int kv = kv0 + j * 8 + 2 * t + (r & 1);
                    int rh = r >> 1;
                    int idx = (yq[mt][rh] - (kv >> 5) + 31) * 63 + (xq[mt][rh] - (kv & 31) + 31);
                    sc[mt][j][r] += s_bias[idx];
                }

#pragma unroll
        for (int mt = 0; mt < 2; mt++)
#pragma unroll
            for (int rh = 0; rh < 2; rh++) {
                float tm = sc[mt][0][2 * rh];
#pragma unroll
                for (int j = 0; j < 4; j++) {
                    tm = fmaxf(tm, sc[mt][j][2 * rh]);
                    tm = fmaxf(tm, sc[mt][j][2 * rh + 1]);
                }
                tm = fmaxf(tm, __shfl_xor_sync(0xffffffffu, tm, 1));
                tm = fmaxf(tm, __shfl_xor_sync(0xffffffffu, tm, 2));
                float mo = m[mt][rh];
                float mn = fmaxf(mo, tm);
                float scale = __expf(mo - mn);
                m[mt][rh] = mn;
                l[mt][rh] *= scale;
#pragma unroll
                for (int n = 0; n < 4; n++) {
                    o[mt][n][2 * rh]     *= scale;
                    o[mt][n][2 * rh + 1] *= scale;
                }
            }
#pragma unroll
        for (int mt = 0; mt < 2; mt++)
#pragma unroll
            for (int j = 0; j < 4; j++)
#pragma unroll
                for (int r = 0; r < 4; r++) {
                    float p = __expf(sc[mt][j][r] - m[mt][r >> 1]);
                    sc[mt][j][r] = p;
                    l[mt][r >> 1] += p;
                }

#pragma unroll
        for (int kk = 0; kk < 2; kk++) {
            uint32_t vf[2][4][2];
#pragma unroll
            for (int sp = 0; sp < 2; sp++)
#pragma unroll
                for (int n = 0; n < 4; n++) {
                    vf[sp][n][0] = sV[sp][n * 8 + g][kk * 8 + t];
                    vf[sp][n][1] = sV[sp][n * 8 + g][kk * 8 + 4 + t];
                }
#pragma unroll
            for (int mt = 0; mt < 2; mt++) {
                uint32_t pf[2][4];
                split2(sc[mt][2 * kk][0],     sc[mt][2 * kk][1],     pf[0][0], pf[1][0]);
                split2(sc[mt][2 * kk][2],     sc[mt][2 * kk][3],     pf[0][1], pf[1][1]);
                split2(sc[mt][2 * kk + 1][0], sc[mt][2 * kk + 1][1], pf[0][2], pf[1][2]);
                split2(sc[mt][2 * kk + 1][2], sc[mt][2 * kk + 1][3], pf[0][3], pf[1][3]);
#pragma unroll
                for (int n = 0; n < 4; n++) {
                    mma16816(o[mt][n], pf[0], vf[0][n]);
                    mma16816(o[mt][n], pf[1], vf[0][n]);
                    mma16816(o[mt][n], pf[0], vf[1][n]);
                }
            }
        }
    }

    float linv[2][2];
#pragma unroll
    for (int mt = 0; mt < 2; mt++)
#pragma unroll
        for (int rh = 0; rh < 2; rh++) {
            float ls = l[mt][rh];
            ls += __shfl_xor_sync(0xffffffffu, ls, 1);
            ls += __shfl_xor_sync(0xffffffffu, ls, 2);
            linv[mt][rh] = 1.f / ls;
        }
    float* ao = &g_attn[(b * 256 + h * DHEAD) * NTOK];
#pragma unroll
    for (int mt = 0; mt < 2; mt++)
#pragma unroll
        for (int n = 0; n < 4; n++)
#pragma unroll
            for (int r = 0; r < 4; r++) {
                int q = qw0 + mt * 16 + g + (r >> 1) * 8;
                int d = n * 8 + 2 * t + (r & 1);
                ao[d * NTOK + q] = o[mt][n][r] * linv[mt][r >> 1];
            }
}

// ---------------- 5) 1x1 output projection ----------------
__global__ void outproj_kernel(const float* __restrict__ bo, float* __restrict__ out) {
    const int nt = blockIdx.x;
    const int b  = blockIdx.y;
    const int oc = threadIdx.x;

    __shared__ __align__(16) float s_a[256 * 32];
    for (int e = oc; e < 8192; e += 256) {
        int c = e >> 5, px = e & 31;
        s_a[e] = g_attn[(b * 256 + c) * NTOK + nt * 32 + px];
    }
    __syncthreads();

    ull acc[16];
#pragma unroll
    for (int p = 0; p < 16; p++) acc[p] = 0ull;

    for (int c = 0; c < 256; c++) {
        float wv = g_woT[c * 256 + oc];
        ull w2 = pack2(wv, wv);
        const ulonglong2* arow2 = reinterpret_cast<const ulonglong2*>(&s_a[c * 32]);
#pragma unroll
        for (int p8 = 0; p8 < 8; p8++) {
            ulonglong2 vv = arow2[p8];
            ffma2(acc[2 * p8],     w2, vv.x);
            ffma2(acc[2 * p8 + 1], w2, vv.y);
        }
    }

    const float bb = bo[oc];
    float* op = out + (b * 256 + oc) * NTOK + nt * 32;
#pragma unroll
    for (int p = 0; p < 16; p += 2) {
        float4 v4 = make_float4(lo2(acc[p]) + bb,     hi2(acc[p]) + bb,
                                lo2(acc[p + 1]) + bb, hi2(acc[p + 1]) + bb);
        *reinterpret_cast<float4*>(op + 2 * p) = v4;
    }
}

// ---------------- launch ----------------
extern "C" void kernel_launch(void* const* d_in, const int* in_sizes, int n_in,
                              void* d_out, int out_size) {
    const float* x  = (const float*)d_in[0];
    const float* wq = (const float*)d_in[1];
    const float* wk = (const float*)d_in[2];
    const float* wv = (const float*)d_in[3];
    const float* gq = (const float*)d_in[4];
    const float* bq = (const float*)d_in[5];
    const float* gk = (const float*)d_in[6];
    const float* bk = (const float*)d_in[7];
    const float* gv = (const float*)d_in[8];
    const float* bv = (const float*)d_in[9];
    const float* bt = (const float*)d_in[10];
    const float* wo = (const float*)d_in[11];
    const float* bo = (const float*)d_in[12];
    float* out = (float*)d_out;

    prep_w_kernel<<<dim3(64, 9, 3), 256>>>(wq, wk, wv);
    prep_x_kernel<<<dim3(34, BATCH), 256>>>(x);
    transpose_wo_kernel<<<dim3(8, 8), dim3(32, 8)>>>(wo);
    conv_mma_kernel<<<dim3(16, 3, BATCH), 256>>>();
    gn_gelu_kernel<<<dim3(8, BATCH, 3), 256>>>(gq, bq, gk, bk, gv, bv);
    attn_kernel<<<dim3(8, HEADS, BATCH), 128>>>(bt);
    outproj_kernel<<<dim3(32, BATCH), 256>>>(bo, out);
}

// round 14
// speedup vs baseline: 1.1573x; 1.1573x over previous
#include <cuda_runtime.h>
#include <cuda_bf16.h>
#include <cstdint>
#include <cstring>

typedef unsigned long long ull;

// Problem constants
#define BATCH 8
#define CHAN  256
#define HEADS 8
#define DHEAD 32
#define NTOK  1024
#define NPER  262144
#define BIASN 3969

// ---------------- scratch ----------------
// W fragments: [p][tap][split][kc(16)][npair(16)][lane(32)][2 frag x 8B]
__device__ __align__(16) __nv_bfloat16 g_wfragB[3*9*2*16*32*32*4];
// X transposed+padded bf16 split: [b][split][y(34)][x(34)][c(256)]
__device__ __align__(16) __nv_bfloat16 g_xbfT[8*2*34*34*256];
__device__ __align__(16) float g_woT[256*256];                 // [c][o]
__device__ __align__(16) float g_act[3][BATCH*NPER];           // conv->gelu activations
__device__ __align__(16) float g_part[3][BATCH][16][2];        // GN partials (16 ntiles)
__device__ __align__(16) float g_attn[BATCH*NPER];

// ---------------- f32x2 helpers ----------------
__device__ __forceinline__ void ffma2(ull& d, ull a, ull b) {
    asm("fma.rn.f32x2 %0, %1, %2, %0;" : "+l"(d) : "l"(a), "l"(b));
}
__device__ __forceinline__ ull pack2(float a, float b) {
    ull u; asm("mov.b64 %0, {%1,%2};" : "=l"(u) : "f"(a), "f"(b)); return u;
}
__device__ __forceinline__ float lo2(ull u) { return __int_as_float((int)(unsigned)u); }
__device__ __forceinline__ float hi2(ull u) { return __int_as_float((int)(u >> 32)); }

// ---------------- warp mma helper (bf16, fp32 accum) ----------------
__device__ __forceinline__ void mma16816(float* c, const uint32_t* a, const uint32_t* b) {
    asm volatile("mma.sync.aligned.m16n8k16.row.col.f32.bf16.bf16.f32 "
        "{%0,%1,%2,%3}, {%4,%5,%6,%7}, {%8,%9}, {%0,%1,%2,%3};"
        : "+f"(c[0]), "+f"(c[1]), "+f"(c[2]), "+f"(c[3])
        : "r"(a[0]), "r"(a[1]), "r"(a[2]), "r"(a[3]), "r"(b[0]), "r"(b[1]));
}

// split two f32 into bf16x2 hi-word and lo-word
__device__ __forceinline__ void split2(float v0, float v1, uint32_t& hi, uint32_t& lo) {
    __nv_bfloat16 h0 = __float2bfloat16(v0), h1 = __float2bfloat16(v1);
    __nv_bfloat16 l0 = __float2bfloat16(v0 - __bfloat162float(h0));
    __nv_bfloat16 l1 = __float2bfloat16(v1 - __bfloat162float(h1));
    __nv_bfloat162 ph; ph.x = h0; ph.y = h1;
    __nv_bfloat162 pl; pl.x = l0; pl.y = l1;
    hi = *reinterpret_cast<uint32_t*>(&ph);
    lo = *reinterpret_cast<uint32_t*>(&pl);
}

// ---------------- 1a) weight prep, ic-permuted fragment order ----------------
__global__ void prep_w_kernel(const float* __restrict__ wq,
                              const float* __restrict__ wk,
                              const float* __restrict__ wv) {
    const int sub = threadIdx.x >> 5, lane = threadIdx.x & 31;
    const int fi = blockIdx.x * 8 + sub;
    const int kc = fi >> 5, ntile = fi & 31;
    const int tap = blockIdx.y, p = blockIdx.z;
    const float* w = (p == 0) ? wq : (p == 1) ? wk : wv;
    const int t = lane & 3, g = lane >> 2;
    const int oc = ntile * 8 + g;
    const int k0 = kc * 16 + t * 4;
    const int npair = ntile >> 1, half = ntile & 1;

    float v0 = w[oc * 2304 + (k0    ) * 9 + tap];
    float v1 = w[oc * 2304 + (k0 + 1) * 9 + tap];
    float v2 = w[oc * 2304 + (k0 + 2) * 9 + tap];
    float v3 = w[oc * 2304 + (k0 + 3) * 9 + tap];

    __nv_bfloat16 h0 = __float2bfloat16(v0), h1 = __float2bfloat16(v1);
    __nv_bfloat16 h2 = __float2bfloat16(v2), h3 = __float2bfloat16(v3);
    __nv_bfloat16 l0 = __float2bfloat16(v0 - __bfloat162float(h0));
    __nv_bfloat16 l1 = __float2bfloat16(v1 - __bfloat162float(h1));
    __nv_bfloat16 l2 = __float2bfloat16(v2 - __bfloat162float(h2));
    __nv_bfloat16 l3 = __float2bfloat16(v3 - __bfloat162float(h3));

    int slot = (((((p * 9 + tap) * 2 + 0) * 16 + kc) * 16 + npair) * 32 + lane) * 2 + half;
    __nv_bfloat16* dh = g_wfragB + slot * 4;
    dh[0] = h0; dh[1] = h1; dh[2] = h2; dh[3] = h3;
    __nv_bfloat16* dl = dh + 16 * 32 * 32 * 4;
    dl[0] = l0; dl[1] = l1; dl[2] = l2; dl[3] = l3;
}

// ---------------- 1b) input transpose + pad + bf16-split ----------------
__global__ void prep_x_kernel(const float* __restrict__ x) {
    const int y = blockIdx.x, b = blockIdx.y, c = threadIdx.x;
    __shared__ float s_t[256][33];
    const bool rowvalid = (y >= 1 && y <= 32);
    if (rowvalid) {
        const float* src = x + ((b * 256 + c) * 32 + (y - 1)) * 32;
#pragma unroll
        for (int i = 0; i < 8; i++) {
            float4 v = reinterpret_cast<const float4*>(src)[i];
            s_t[c][i * 4 + 0] = v.x; s_t[c][i * 4 + 1] = v.y;
            s_t[c][i * 4 + 2] = v.z; s_t[c][i * 4 + 3] = v.w;
        }
    }
    __syncthreads();
    for (int xx = 0; xx < 34; xx++) {
        float v = (rowvalid && xx >= 1 && xx <= 32) ? s_t[c][xx - 1] : 0.f;
        __nv_bfloat16 hi = __float2bfloat16(v);
        __nv_bfloat16 lo = __float2bfloat16(v - __bfloat162float(hi));
        int base = (((b * 2) * 34 + y) * 34 + xx) * 256 + c;
        g_xbfT[base]              = hi;
        g_xbfT[base + 34*34*256]  = lo;
    }
}

// ---------------- 1c) wo transpose ----------------
__global__ void transpose_wo_kernel(const float* __restrict__ wo) {
    __shared__ float tile[32][33];
    const int c0 = blockIdx.x * 32, o0 = blockIdx.y * 32;
#pragma unroll
    for (int i = 0; i < 4; i++)
        tile[threadIdx.y + i * 8][threadIdx.x] = wo[(o0 + threadIdx.y + i * 8) * 256 + c0 + threadIdx.x];
    __syncthreads();
#pragma unroll
    for (int i = 0; i < 4; i++)
        g_woT[(c0 + threadIdx.y + i * 8) * 256 + o0 + threadIdx.x] =
            tile[threadIdx.x][threadIdx.y + i * 8];
}

// ---------------- conv fragment load helpers ----------------
__device__ __forceinline__ void load_afrag(uint32_t afr[2][2][4],
                                           const __nv_bfloat16* const abase[2][2],
                                           int kofs) {
#pragma unroll
    for (int mt = 0; mt < 2; mt++)
#pragma unroll
        for (int sp = 0; sp < 2; sp++) {
            const __nv_bfloat16* xp = abase[mt][sp] + kofs;
            ull v0 = *reinterpret_cast<const ull*>(xp);
            ull v1 = *reinterpret_cast<const ull*>(xp + 2048);
            afr[sp][mt][0] = (uint32_t)v0;
            afr[sp][mt][2] = (uint32_t)(v0 >> 32);
            afr[sp][mt][1] = (uint32_t)v1;
            afr[sp][mt][3] = (uint32_t)(v1 >> 32);
        }
}
__device__ __forceinline__ void load_bfrag(uint32_t bfr[2][8][2],
                                           const uint4* const bbase[2],
                                           int kofs) {
#pragma unroll
    for (int sp = 0; sp < 2; sp++) {
        const uint4* wb = bbase[sp] + kofs;
#pragma unroll
        for (int n4 = 0; n4 < 4; n4++) {
            uint4 v = wb[n4 * 32];
            bfr[sp][2 * n4][0]     = v.x;
            bfr[sp][2 * n4][1]     = v.y;
            bfr[sp][2 * n4 + 1][0] = v.z;
            bfr[sp][2 * n4 + 1][1] = v.w;
        }
    }
}

// ---------------- 2) conv via mma.sync, kc-pipelined (double-buffered frags) ----
// grid (16 pxtiles, 3 p, 8 b), block 256 (8 warps = 2m x 4n)
__global__ void __launch_bounds__(256) conv_mma_kernel() {
    const int nt  = blockIdx.x;
    const int p   = blockIdx.y;
    const int b   = blockIdx.z;
    const int tid = threadIdx.x, warp = tid >> 5, lane = tid & 31;
    const int wm = warp & 1, wn = warp >> 1;
    const int g = lane >> 2, t = lane & 3;
    const int px_warp = nt * 64 + wm * 32;

    float acc[2][8][4];
#pragma unroll
    for (int mt = 0; mt < 2; mt++)
#pragma unroll
        for (int n8 = 0; n8 < 8; n8++)
#pragma unroll
            for (int r = 0; r < 4; r++) acc[mt][n8][r] = 0.f;

    uint32_t afr[2][2][2][4];   // [buf][sp][mt][4]
    uint32_t bfr[2][2][8][2];   // [buf][sp][n8][2]

    for (int tap = 0; tap < 9; tap++) {
        const int ky = tap / 3, kx = tap - ky * 3;

        const __nv_bfloat16* abase[2][2];
#pragma unroll
        for (int mt = 0; mt < 2; mt++) {
            const int px = px_warp + mt * 16 + g;
            const int y  = (px >> 5) + ky;
            const int x  = (px & 31) + kx;
#pragma unroll
            for (int sp = 0; sp < 2; sp++)
                abase[mt][sp] = g_xbfT + (((b * 2 + sp) * 34 + y) * 34 + x) * 256 + t * 4;
        }
        const uint4* bbase[2];
#pragma unroll
        for (int sp = 0; sp < 2; sp++)
            bbase[sp] = reinterpret_cast<const uint4*>(g_wfragB) +
                ((((p * 9 + tap) * 2 + sp) * 16) * 16 + wn * 4) * 32 + lane;

        // prologue: load kc=0 into buf 0
        load_afrag(afr[0], abase, 0);
        load_bfrag(bfr[0], bbase, 0);

#pragma unroll 2
        for (int kc = 0; kc < 16; kc++) {
            const int cur = kc & 1, nxt = cur ^ 1;
            if (kc < 15) {
                load_afrag(afr[nxt], abase, (kc + 1) * 16);
                load_bfrag(bfr[nxt], bbase, (kc + 1) * 512);
            }
#pragma unroll
            for (int combo = 0; combo < 3; combo++) {
                const int ws = combo >> 1, xs = combo & 1;
#pragma unroll
                for (int mt = 0; mt < 2; mt++)
#pragma unroll
                    for (int n8 = 0; n8 < 8; n8++)
                        mma16816(acc[mt][n8], afr[cur][xs][mt], bfr[cur][ws][n8]);
            }
        }
    }

    float s = 0.f, sq = 0.f;
#pragma unroll
    for (int mt = 0; mt < 2; mt++)
#pragma unroll
        for (int n8 = 0; n8 < 8; n8++)
#pragma unroll
            for (int r = 0; r < 4; r++) {
                float v  = acc[mt][n8][r];
                int   px = px_warp + mt * 16 + g + ((r >> 1) << 3);
                int   oc = wn * 64 + n8 * 8 + t * 2 + (r & 1);
                g_act[p][(b * 256 + oc) * 1024 + px] = v;
                s += v; sq += v * v;
            }
    __shared__ float red[512];
    red[tid] = s; red[tid + 256] = sq;
    __syncthreads();
    for (int st = 128; st > 0; st >>= 1) {
        if (tid < st) { red[tid] += red[tid + st]; red[tid + 256] += red[tid + 256 + st]; }
        __syncthreads();
    }
    if (tid == 0) {
        g_part[p][b][nt][0] = red[0];
        g_part[p][b][nt][1] = red[256];
    }
}

// ---------------- 3) GroupNorm(1) + exact GELU ----------------
__global__ void gn_gelu_kernel(const float* __restrict__ gq, const float* __restrict__ bq,
                               const float* __restrict__ gk, const float* __restrict__ bk,
                               const float* __restrict__ gv, const float* __restrict__ bv) {
    const int chunk = blockIdx.x;
    const int b     = blockIdx.y;
    const int p     = blockIdx.z;
    const float* gg = (p == 0) ? gq : (p == 1) ? gk : gv;
    const float* bb = (p == 0) ? bq : (p == 1) ? bk : bv;

    __shared__ float s_mu, s_rs;
    if (threadIdx.x < 16) {
        float s  = g_part[p][b][threadIdx.x][0];
        float sq = g_part[p][b][threadIdx.x][1];
#pragma unroll
        for (int o = 8; o > 0; o >>= 1) {
            s  += __shfl_down_sync(0x0000ffffu, s,  o);
            sq += __shfl_down_sync(0x0000ffffu, sq, o);
        }
        if (threadIdx.x == 0) {
            float mu  = s / (float)NPER;
            float var = sq / (float)NPER - mu * mu;
            s_mu = mu;
            s_rs = rsqrtf(var + 1e-6f);
        }
    }
    __syncthreads();
    const float mu = s_mu, rs = s_rs;

    float* base = &g_act[p][b * NPER + chunk * 32768];
    for (int i = threadIdx.x; i < 8192; i += 256) {
        float4 v = reinterpret_cast<float4*>(base)[i];
        int c = (chunk * 32768 + i * 4) >> 10;
        float gc = gg[c], bc = bb[c];
        float t0 = (v.x - mu) * rs * gc + bc;
        float t1 = (v.y - mu) * rs * gc + bc;
        float t2 = (v.z - mu) * rs * gc + bc;
        float t3 = (v.w - mu) * rs * gc + bc;
        v.x = 0.5f * t0 * (1.0f + erff(t0 * 0.70710678118654752f));
        v.y = 0.5f * t1 * (1.0f + erff(t1 * 0.70710678118654752f));
        v.z = 0.5f * t2 * (1.0f + erff(t2 * 0.70710678118654752f));
        v.w = 0.5f * t3 * (1.0f + erff(t3 * 0.70710678118654752f));
        reinterpret_cast<float4*>(base)[i] = v;
    }
}

// ---------------- 4) tensor-core flash attention (R12 version) ----------------
__global__ void __launch_bounds__(128) attn_kernel(const float* __restrict__ bias_table) {
    const int qt = blockIdx.x, h = blockIdx.y, b = blockIdx.z;
    const int tid = threadIdx.x, warp = tid >> 5, lane = tid & 31;
    const int g = lane >> 2, t = lane & 3;
    const int qw0 = qt * 128 + warp * 32;

    __shared__ float    s_bias[BIASN + 3];
    __shared__ uint32_t sK[2][32][17];
    __shared__ uint32_t sV[2][32][17];

    for (int i = tid; i < BIASN; i += 128)
        s_bias[i] = bias_table[i * HEADS + h];

    const float* aq = &g_act[0][(b * 256 + h * DHEAD) * NTOK];
    const float* ak = &g_act[1][(b * 256 + h * DHEAD) * NTOK];
    const float* av = &g_act[2][(b * 256 + h * DHEAD) * NTOK];

    uint32_t qf[2][2][2][4];
#pragma unroll
    for (int mt = 0; mt < 2; mt++) {
        const int row0 = qw0 + mt * 16 + g;
#pragma unroll
        for (int kc = 0; kc < 2; kc++) {
            const int kd = kc * 16;
            float a00 = aq[(kd + 2 * t    ) * NTOK + row0];
            float a01 = aq[(kd + 2 * t + 1) * NTOK + row0];
            float a10 = aq[(kd + 2 * t    ) * NTOK + row0 + 8];
            float a11 = aq[(kd + 2 * t + 1) * NTOK + row0 + 8];
            float a20 = aq[(kd + 8 + 2 * t    ) * NTOK + row0];
            float a21 = aq[(kd + 8 + 2 * t + 1) * NTOK + row0];
            float a30 = aq[(kd + 8 + 2 * t    ) * NTOK + row0 + 8];
            float a31 = aq[(kd + 8 + 2 * t + 1) * NTOK + row0 + 8];
            split2(a00, a01, qf[0][mt][kc][0], qf[1][mt][kc][0]);
            split2(a10, a11, qf[0][mt][kc][1], qf[1][mt][kc][1]);
            split2(a20, a21, qf[0][mt][kc][2], qf[1][mt][kc][2]);
            split2(a30, a31, qf[0][mt][kc][3], qf[1][mt][kc][3]);
        }
    }

    int yq[2][2], xq[2][2];
#pragma unroll
    for (int mt = 0; mt < 2; mt++)
#pragma unroll
        for (int rh = 0; rh < 2; rh++) {
            int q = qw0 + mt * 16 + g + rh * 8;
            yq[mt][rh] = q >> 5; xq[mt][rh] = q & 31;
        }

    float m[2][2], l[2][2];
    float o[2][4][4];
#pragma unroll
    for (int mt = 0; mt < 2; mt++)
#pragma unroll
        for (int rh = 0; rh < 2; rh++) { m[mt][rh] = -1e30f; l[mt][rh] = 0.f; }
#pragma unroll
    for (int mt = 0; mt < 2; mt++)
#pragma unroll
        for (int n = 0; n < 4; n++)
#pragma unroll
            for (int r = 0; r < 4; r++) o[mt][n][r] = 0.f;

    for (int kt = 0; kt < 32; kt++) {
        const int kv0 = kt * 32;
        __syncthreads();
        for (int e = tid; e < 512; e += 128) {
            int kv = e & 31, dp = e >> 5;
            float f0 = ak[(2 * dp)     * NTOK + kv0 + kv];
            float f1 = ak[(2 * dp + 1) * NTOK + kv0 + kv];
            uint32_t hi, lo;
            split2(f0, f1, hi, lo);
            sK[0][kv][dp] = hi; sK[1][kv][dp] = lo;
        }
        for (int e = tid; e < 512; e += 128) {
            int kvp = e & 15, d = e >> 4;
            float2 vv = *reinterpret_cast<const float2*>(&av[d * NTOK + kv0 + 2 * kvp]);
            uint32_t hi, lo;
            split2(vv.x, vv.y, hi, lo);
            sV[0][d][kvp] = hi; sV[1][d][kvp] = lo;
        }
        __syncthreads();

        float sc[2][4][4];
#pragma unroll
        for (int mt = 0; mt < 2; mt++)
#pragma unroll
            for (int j = 0; j < 4; j++)
#pragma unroll
                for (int r = 0; r < 4; r++) sc[mt][j][r] = 0.f;

#pragma unroll
        for (int kc = 0; kc < 2; kc++) {
            uint32_t kf[2][4][2];
#pragma unroll
            for (int sp = 0; sp < 2; sp++)
#pragma unroll
                for (int j = 0; j < 4; j++) {
                    kf[sp][j][0] = sK[sp][j * 8 + g][kc * 8 + t];
                    kf[sp][j][1] = sK[sp][j * 8 + g][kc * 8 + 4 + t];
                }
#pragma unroll
            for (int mt = 0; mt < 2; mt++)
#pragma unroll
                for (int j = 0; j < 4; j++) {
                    mma16816(sc[mt][j], qf[0][mt][kc], kf[0][j]);
                    mma16816(sc[mt][j], qf[1][mt][kc], kf[0][j]);
                    mma16816(sc[mt][j], qf[0][mt][kc], kf[1][j]);
                }
        }

#pragma unroll
        for (int mt = 0; mt < 2; mt++)
#pragma unroll
            for (int j = 0; j < 4; j++)
#pragma unroll
                for (int r = 0; r < 4; r++) {
                    int kv = kv0 + j * 8 + 2 * t + (r & 1);
                    int rh = r >> 1;
                    int idx = (yq[mt][rh] - (kv >> 5) + 31) * 63 + (xq[mt][rh] - (kv & 31) + 31);
                    sc[mt][j][r] += s_bias[idx];
                }

#pragma unroll
        for (int mt = 0; mt < 2; mt++)
#pragma unroll
            for (int rh = 0; rh < 2; rh++) {
                float tm = sc[mt][0][2 * rh];
#pragma unroll
                for (int j = 0; j < 4; j++) {
                    tm = fmaxf(tm, sc[mt][j][2 * rh]);
                    tm = fmaxf(tm, sc[mt][j][2 * rh + 1]);
                }
                tm = fmaxf(tm, __shfl_xor_sync(0xffffffffu, tm, 1));
                tm = fmaxf(tm, __shfl_xor_sync(0xffffffffu, tm, 2));
                float mo = m[mt][rh];
                float mn = fmaxf(mo, tm);
                float scale = __expf(mo - mn);
                m[mt][rh] = mn;
                l[mt][rh] *= scale;
#pragma unroll
                for (int n = 0; n < 4; n++) {
                    o[mt][n][2 * rh]     *= scale;
                    o[mt][n][2 * rh + 1] *= scale;
                }
            }
#pragma unroll
        for (int mt = 0; mt < 2; mt++)
#pragma unroll
            for (int j = 0; j < 4; j++)
#pragma unroll
                for (int r = 0; r < 4; r++) {
                    float p = __expf(sc[mt][j][r] - m[mt][r >> 1]);
                    sc[mt][j][r] = p;
                    l[mt][r >> 1] += p;
                }

#pragma unroll
        for (int kk = 0; kk < 2; kk++) {
            uint32_t vf[2][4][2];
#pragma unroll
            for (int sp = 0; sp < 2; sp++)
#pragma unroll
                for (int n = 0; n < 4; n++) {
                    vf[sp][n][0] = sV[sp][n * 8 + g][kk * 8 + t];
                    vf[sp][n][1] = sV[sp][n * 8 + g][kk * 8 + 4 + t];
                }
#pragma unroll
            for (int mt = 0; mt < 2; mt++) {
                uint32_t pf[2][4];
                split2(sc[mt][2 * kk][0],     sc[mt][2 * kk][1],     pf[0][0], pf[1][0]);
                split2(sc[mt][2 * kk][2],     sc[mt][2 * kk][3],     pf[0][1], pf[1][1]);
                split2(sc[mt][2 * kk + 1][0], sc[mt][2 * kk + 1][1], pf[0][2], pf[1][2]);
                split2(sc[mt][2 * kk + 1][2], sc[mt][2 * kk + 1][3], pf[0][3], pf[1][3]);
#pragma unroll
                for (int n = 0; n < 4; n++) {
                    mma16816(o[mt][n], pf[0], vf[0][n]);
                    mma16816(o[mt][n], pf[1], vf[0][n]);
                    mma16816(o[mt][n], pf[0], vf[1][n]);
                }
            }
        }
    }

    float linv[2][2];
#pragma unroll
    for (int mt = 0; mt < 2; mt++)
#pragma unroll
        for (int rh = 0; rh < 2; rh++) {
            float ls = l[mt][rh];
            ls += __shfl_xor_sync(0xffffffffu, ls, 1);
            ls += __shfl_xor_sync(0xffffffffu, ls, 2);
            linv[mt][rh] = 1.f / ls;
        }
    float* ao = &g_attn[(b * 256 + h * DHEAD) * NTOK];
#pragma unroll
    for (int mt = 0; mt < 2; mt++)
#pragma unroll
        for (int n = 0; n < 4; n++)
#pragma unroll
            for (int r = 0; r < 4; r++) {
                int q = qw0 + mt * 16 + g + (r >> 1) * 8;
                int d = n * 8 + 2 * t + (r & 1);
                ao[d * NTOK + q] = o[mt][n][r] * linv[mt][r >> 1];
            }
}

// ---------------- 5) 1x1 output projection ----------------
__global__ void outproj_kernel(const float* __restrict__ bo, float* __restrict__ out) {
    const int nt = blockIdx.x;
    const int b  = blockIdx.y;
    const int oc = threadIdx.x;

    __shared__ __align__(16) float s_a[256 * 32];
    for (int e = oc; e < 8192; e += 256) {
        int c = e >> 5, px = e & 31;
        s_a[e] = g_attn[(b * 256 + c) * NTOK + nt * 32 + px];
    }
    __syncthreads();

    ull acc[16];
#pragma unroll
    for (int p = 0; p < 16; p++) acc[p] = 0ull;

    for (int c = 0; c < 256; c++) {
        float wv = g_woT[c * 256 + oc];
        ull w2 = pack2(wv, wv);
        const ulonglong2* arow2 = reinterpret_cast<const ulonglong2*>(&s_a[c * 32]);
#pragma unroll
        for (int p8 = 0; p8 < 8; p8++) {
            ulonglong2 vv = arow2[p8];
            ffma2(acc[2 * p8],     w2, vv.x);
            ffma2(acc[2 * p8 + 1], w2, vv.y);
        }
    }

    const float bb = bo[oc];
    float* op = out + (b * 256 + oc) * NTOK + nt * 32;
#pragma unroll
    for (int p = 0; p < 16; p += 2) {
        float4 v4 = make_float4(lo2(acc[p]) + bb,     hi2(acc[p]) + bb,
                                lo2(acc[p + 1]) + bb, hi2(acc[p + 1]) + bb);
        *reinterpret_cast<float4*>(op + 2 * p) = v4;
    }
}

// ---------------- launch ----------------
extern "C" void kernel_launch(void* const* d_in, const int* in_sizes, int n_in,
                              void* d_out, int out_size) {
    const float* x  = (const float*)d_in[0];
    const float* wq = (const float*)d_in[1];
    const float* wk = (const float*)d_in[2];
    const float* wv = (const float*)d_in[3];
    const float* gq = (const float*)d_in[4];
    const float* bq = (const float*)d_in[5];
    const float* gk = (const float*)d_in[6];
    const float* bk = (const float*)d_in[7];
    const float* gv = (const float*)d_in[8];
    const float* bv = (const float*)d_in[9];
    const float* bt = (const float*)d_in[10];
    const float* wo = (const float*)d_in[11];
    const float* bo = (const float*)d_in[12];
    float* out = (float*)d_out;

    prep_w_kernel<<<dim3(64, 9, 3), 256>>>(wq, wk, wv);
    prep_x_kernel<<<dim3(34, BATCH), 256>>>(x);
    transpose_wo_kernel<<<dim3(8, 8), dim3(32, 8)>>>(wo);
    conv_mma_kernel<<<dim3(16, 3, BATCH), 256>>>();
    gn_gelu_kernel<<<dim3(8, BATCH, 3), 256>>>(gq, bq, gk, bk, gv, bv);
    attn_kernel<<<dim3(8, HEADS, BATCH), 128>>>(bt);
    outproj_kernel<<<dim3(32, BATCH), 256>>>(bo, out);
}

// round 15
// speedup vs baseline: 1.1648x; 1.0065x over previous
#include <cuda_runtime.h>
#include <cuda_bf16.h>
#include <cstdint>
#include <cstring>

typedef unsigned long long ull;

// Problem constants
#define BATCH 8
#define CHAN  256
#define HEADS 8
#define DHEAD 32
#define NTOK  1024
#define NPER  262144
#define BIASN 3969

// ---------------- scratch ----------------
// W fragments: [p][tap][split][kc(16)][npair(16)][lane(32)][2 frag x 8B]
__device__ __align__(16) __nv_bfloat16 g_wfragB[3*9*2*16*32*32*4];
// X transposed+padded bf16 split: [b][split][y(34)][x(34)][c(256)]
__device__ __align__(16) __nv_bfloat16 g_xbfT[8*2*34*34*256];
__device__ __align__(16) float g_woT[256*256];                 // [c][o]
__device__ __align__(16) float g_act[3][BATCH*NPER];           // conv outputs (pre-GN)
__device__ __align__(16) float g_part[3][BATCH][16][2];        // GN partials (16 ntiles)
__device__ __align__(16) float g_attn[BATCH*NPER];
// packed post-GN/GELU activations (bf16x2 words, hi/lo splits)
// Q,K: d-pair packed [p][b][split][cp(128)][n(1024)]
__device__ __align__(16) uint32_t g_qkp[2][BATCH][2][128*1024];
// V: token-pair packed [b][split][c(256)][np(512)]
__device__ __align__(16) uint32_t g_vp[BATCH][2][256*512];

// ---------------- f32x2 helpers ----------------
__device__ __forceinline__ void ffma2(ull& d, ull a, ull b) {
    asm("fma.rn.f32x2 %0, %1, %2, %0;" : "+l"(d) : "l"(a), "l"(b));
}
__device__ __forceinline__ ull pack2(float a, float b) {
    ull u; asm("mov.b64 %0, {%1,%2};" : "=l"(u) : "f"(a), "f"(b)); return u;
}
__device__ __forceinline__ float lo2(ull u) { return __int_as_float((int)(unsigned)u); }
__device__ __forceinline__ float hi2(ull u) { return __int_as_float((int)(u >> 32)); }

// ---------------- warp mma helper (bf16, fp32 accum) ----------------
__device__ __forceinline__ void mma16816(float* c, const uint32_t* a, const uint32_t* b) {
    asm volatile("mma.sync.aligned.m16n8k16.row.col.f32.bf16.bf16.f32 "
        "{%0,%1,%2,%3}, {%4,%5,%6,%7}, {%8,%9}, {%0,%1,%2,%3};"
        : "+f"(c[0]), "+f"(c[1]), "+f"(c[2]), "+f"(c[3])
        : "r"(a[0]), "r"(a[1]), "r"(a[2]), "r"(a[3]), "r"(b[0]), "r"(b[1]));
}

// split two f32 into bf16x2 hi-word and lo-word (element0 = v0)
__device__ __forceinline__ void split2(float v0, float v1, uint32_t& hi, uint32_t& lo) {
    __nv_bfloat16 h0 = __float2bfloat16(v0), h1 = __float2bfloat16(v1);
    __nv_bfloat16 l0 = __float2bfloat16(v0 - __bfloat162float(h0));
    __nv_bfloat16 l1 = __float2bfloat16(v1 - __bfloat162float(h1));
    __nv_bfloat162 ph; ph.x = h0; ph.y = h1;
    __nv_bfloat162 pl; pl.x = l0; pl.y = l1;
    hi = *reinterpret_cast<uint32_t*>(&ph);
    lo = *reinterpret_cast<uint32_t*>(&pl);
}

// ---------------- 1a) weight prep, ic-permuted fragment order ----------------
__global__ void prep_w_kernel(const float* __restrict__ wq,
                              const float* __restrict__ wk,
                              const float* __restrict__ wv) {
    const int sub = threadIdx.x >> 5, lane = threadIdx.x & 31;
    const int fi = blockIdx.x * 8 + sub;
    const int kc = fi >> 5, ntile = fi & 31;
    const int tap = blockIdx.y, p = blockIdx.z;
    const float* w = (p == 0) ? wq : (p == 1) ? wk : wv;
    const int t = lane & 3, g = lane >> 2;
    const int oc = ntile * 8 + g;
    const int k0 = kc * 16 + t * 4;
    const int npair = ntile >> 1, half = ntile & 1;

    float v0 = w[oc * 2304 + (k0    ) * 9 + tap];
    float v1 = w[oc * 2304 + (k0 + 1) * 9 + tap];
    float v2 = w[oc * 2304 + (k0 + 2) * 9 + tap];
    float v3 = w[oc * 2304 + (k0 + 3) * 9 + tap];

    __nv_bfloat16 h0 = __float2bfloat16(v0), h1 = __float2bfloat16(v1);
    __nv_bfloat16 h2 = __float2bfloat16(v2), h3 = __float2bfloat16(v3);
    __nv_bfloat16 l0 = __float2bfloat16(v0 - __bfloat162float(h0));
    __nv_bfloat16 l1 = __float2bfloat16(v1 - __bfloat162float(h1));
    __nv_bfloat16 l2 = __float2bfloat16(v2 - __bfloat162float(h2));
    __nv_bfloat16 l3 = __float2bfloat16(v3 - __bfloat162float(h3));

    int slot = (((((p * 9 + tap) * 2 + 0) * 16 + kc) * 16 + npair) * 32 + lane) * 2 + half;
    __nv_bfloat16* dh = g_wfragB + slot * 4;
    dh[0] = h0; dh[1] = h1; dh[2] = h2; dh[3] = h3;
    __nv_bfloat16* dl = dh + 16 * 32 * 32 * 4;
    dl[0] = l0; dl[1] = l1; dl[2] = l2; dl[3] = l3;
}

// ---------------- 1b) input transpose + pad + bf16-split ----------------
__global__ void prep_x_kernel(const float* __restrict__ x) {
    const int y = blockIdx.x, b = blockIdx.y, c = threadIdx.x;
    __shared__ float s_t[256][33];
    const bool rowvalid = (y >= 1 && y <= 32);
    if (rowvalid) {
        const float* src = x + ((b * 256 + c) * 32 + (y - 1)) * 32;
#pragma unroll
        for (int i = 0; i < 8; i++) {
            float4 v = reinterpret_cast<const float4*>(src)[i];
            s_t[c][i * 4 + 0] = v.x; s_t[c][i * 4 + 1] = v.y;
            s_t[c][i * 4 + 2] = v.z; s_t[c][i * 4 + 3] = v.w;
        }
    }
    __syncthreads();
    for (int xx = 0; xx < 34; xx++) {
        float v = (rowvalid && xx >= 1 && xx <= 32) ? s_t[c][xx - 1] : 0.f;
        __nv_bfloat16 hi = __float2bfloat16(v);
        __nv_bfloat16 lo = __float2bfloat16(v - __bfloat162float(hi));
        int base = (((b * 2) * 34 + y) * 34 + xx) * 256 + c;
        g_xbfT[base]              = hi;
        g_xbfT[base + 34*34*256]  = lo;
    }
}

// ---------------- 1c) wo transpose ----------------
__global__ void transpose_wo_kernel(const float* __restrict__ wo) {
    __shared__ float tile[32][33];
    const int c0 = blockIdx.x * 32, o0 = blockIdx.y * 32;
#pragma unroll
    for (int i = 0; i < 4; i++)
        tile[threadIdx.y + i * 8][threadIdx.x] = wo[(o0 + threadIdx.y + i * 8) * 256 + c0 + threadIdx.x];
    __syncthreads();
#pragma unroll
    for (int i = 0; i < 4; i++)
        g_woT[(c0 + threadIdx.y + i * 8) * 256 + o0 + threadIdx.x] =
            tile[threadIdx.x][threadIdx.y + i * 8];
}

// ---------------- conv fragment load helpers ----------------
__device__ __forceinline__ void load_afrag(uint32_t afr[2][2][4],
                                           const __nv_bfloat16* const abase[2][2],
                                           int kofs) {
#pragma unroll
    for (int mt = 0; mt < 2; mt++)
#pragma unroll
        for (int sp = 0; sp < 2; sp++) {
            const __nv_bfloat16* xp = abase[mt][sp] + kofs;
            ull v0 = *reinterpret_cast<const ull*>(xp);
            ull v1 = *reinterpret_cast<const ull*>(xp + 2048);
            afr[sp][mt][0] = (uint32_t)v0;
            afr[sp][mt][2] = (uint32_t)(v0 >> 32);
            afr[sp][mt][1] = (uint32_t)v1;
            afr[sp][mt][3] = (uint32_t)(v1 >> 32);
        }
}
__device__ __forceinline__ void load_bfrag(uint32_t bfr[2][8][2],
                                           const uint4* const bbase[2],
                                           int kofs) {
#pragma unroll
    for (int sp = 0; sp < 2; sp++) {
        const uint4* wb = bbase[sp] + kofs;
#pragma unroll
        for (int n4 = 0; n4 < 4; n4++) {
            uint4 v = wb[n4 * 32];
            bfr[sp][2 * n4][0]     = v.x;
            bfr[sp][2 * n4][1]     = v.y;
            bfr[sp][2 * n4 + 1][0] = v.z;
            bfr[sp][2 * n4 + 1][1] = v.w;
        }
    }
}

// ---------------- 2) conv via mma.sync, kc-pipelined (R14 + branchless clamp) ----
__global__ void __launch_bounds__(256) conv_mma_kernel() {
    const int nt  = blockIdx.x;
    const int p   = blockIdx.y;
    const int b   = blockIdx.z;
    const int tid = threadIdx.x, warp = tid >> 5, lane = tid & 31;
    const int wm = warp & 1, wn = warp >> 1;
    const int g = lane >> 2, t = lane & 3;
    const int px_warp = nt * 64 + wm * 32;

    float acc[2][8][4];
#pragma unroll
    for (int mt = 0; mt < 2; mt++)
#pragma unroll
        for (int n8 = 0; n8 < 8; n8++)
#pragma unroll
            for (int r = 0; r < 4; r++) acc[mt][n8][r] = 0.f;

    uint32_t afr[2][2][2][4];
    uint32_t bfr[2][2][8][2];

    for (int tap = 0; tap < 9; tap++) {
        const int ky = tap / 3, kx = tap - ky * 3;

        const __nv_bfloat16* abase[2][2];
#pragma unroll
        for (int mt = 0; mt < 2; mt++) {
            const int px = px_warp + mt * 16 + g;
            const int y  = (px >> 5) + ky;
            const int x  = (px & 31) + kx;
#pragma unroll
            for (int sp = 0; sp < 2; sp++)
                abase[mt][sp] = g_xbfT + (((b * 2 + sp) * 34 + y) * 34 + x) * 256 + t * 4;
        }
        const uint4* bbase[2];
#pragma unroll
        for (int sp = 0; sp < 2; sp++)
            bbase[sp] = reinterpret_cast<const uint4*>(g_wfragB) +
                ((((p * 9 + tap) * 2 + sp) * 16) * 16 + wn * 4) * 32 + lane;

        load_afrag(afr[0], abase, 0);
        load_bfrag(bfr[0], bbase, 0);

#pragma unroll 2
        for (int kc = 0; kc < 16; kc++) {
            const int cur = kc & 1, nxt = cur ^ 1;
            const int kn = (kc < 15) ? (kc + 1) : 15;
            load_afrag(afr[nxt], abase, kn * 16);
            load_bfrag(bfr[nxt], bbase, kn * 512);
#pragma unroll
            for (int combo = 0; combo < 3; combo++) {
                const int ws = combo >> 1, xs = combo & 1;
#pragma unroll
                for (int mt = 0; mt < 2; mt++)
#pragma unroll
                    for (int n8 = 0; n8 < 8; n8++)
                        mma16816(acc[mt][n8], afr[cur][xs][mt], bfr[cur][ws][n8]);
            }
        }
    }

    float s = 0.f, sq = 0.f;
#pragma unroll
    for (int mt = 0; mt < 2; mt++)
#pragma unroll
        for (int n8 = 0; n8 < 8; n8++)
#pragma unroll
            for (int r = 0; r < 4; r++) {
                float v  = acc[mt][n8][r];
                int   px = px_warp + mt * 16 + g + ((r >> 1) << 3);
                int   oc = wn * 64 + n8 * 8 + t * 2 + (r & 1);
                g_act[p][(b * 256 + oc) * 1024 + px] = v;
                s += v; sq += v * v;
            }
    __shared__ float red[512];
    red[tid] = s; red[tid + 256] = sq;
    __syncthreads();
    for (int st = 128; st > 0; st >>= 1) {
        if (tid < st) { red[tid] += red[tid + st]; red[tid + 256] += red[tid + 256 + st]; }
        __syncthreads();
    }
    if (tid == 0) {
        g_part[p][b][nt][0] = red[0];
        g_part[p][b][nt][1] = red[256];
    }
}

// ---------------- 3) GroupNorm + GELU + bf16-split packing ----------------
// grid (8 chunks, 8 b, 3 p), block 256. Each block: 16384 output words.
// p in {0,1}: d-pair packed [cp][n]; p==2: token-pair packed [c][np].
__global__ void gn_gelu_kernel(const float* __restrict__ gq, const float* __restrict__ bq,
                               const float* __restrict__ gk, const float* __restrict__ bk,
                               const float* __restrict__ gv, const float* __restrict__ bv) {
    const int chunk = blockIdx.x;
    const int b     = blockIdx.y;
    const int p     = blockIdx.z;
    const float* gg = (p == 0) ? gq : (p == 1) ? gk : gv;
    const float* bb = (p == 0) ? bq : (p == 1) ? bk : bv;

    __shared__ float s_mu, s_rs;
    if (threadIdx.x < 16) {
        float s  = g_part[p][b][threadIdx.x][0];
        float sq = g_part[p][b][threadIdx.x][1];
#pragma unroll
        for (int o = 8; o > 0; o >>= 1) {
            s  += __shfl_down_sync(0x0000ffffu, s,  o);
            sq += __shfl_down_sync(0x0000ffffu, sq, o);
        }
        if (threadIdx.x == 0) {
            float mu  = s / (float)NPER;
            float var = sq / (float)NPER - mu * mu;
            s_mu = mu;
            s_rs = rsqrtf(var + 1e-6f);
        }
    }
    __syncthreads();
    const float mu = s_mu, rs = s_rs;
    const float* act = &g_act[p][b * NPER];

    if (p < 2) {
        uint32_t* dh = &g_qkp[p][b][0][0];
        uint32_t* dl = &g_qkp[p][b][1][0];
        for (int i = threadIdx.x; i < 16384; i += 256) {
            int idx = chunk * 16384 + i;
            int cp = idx >> 10, n = idx & 1023;
            float v0 = act[(2 * cp) * 1024 + n];
            float v1 = act[(2 * cp + 1) * 1024 + n];
            float gc0 = gg[2 * cp], bc0 = bb[2 * cp];
            float gc1 = gg[2 * cp + 1], bc1 = bb[2 * cp + 1];
            float t0 = (v0 - mu) * rs * gc0 + bc0;
            float t1 = (v1 - mu) * rs * gc1 + bc1;
            t0 = 0.5f * t0 * (1.0f + erff(t0 * 0.70710678118654752f));
            t1 = 0.5f * t1 * (1.0f + erff(t1 * 0.70710678118654752f));
            uint32_t hi, lo;
            split2(t0, t1, hi, lo);
            dh[idx] = hi; dl[idx] = lo;
        }
    } else {
        uint32_t* dh = &g_vp[b][0][0];
        uint32_t* dl = &g_vp[b][1][0];
        for (int i = threadIdx.x; i < 16384; i += 256) {
            int idx = chunk * 16384 + i;
            int c = idx >> 9, np = idx & 511;
            float2 vv = *reinterpret_cast<const float2*>(&act[c * 1024 + 2 * np]);
            float gc = gg[c], bc = bb[c];
            float t0 = (vv.x - mu) * rs * gc + bc;
            float t1 = (vv.y - mu) * rs * gc + bc;
            t0 = 0.5f * t0 * (1.0f + erff(t0 * 0.70710678118654752f));
            t1 = 0.5f * t1 * (1.0f + erff(t1 * 0.70710678118654752f));
            uint32_t hi, lo;
            split2(t0, t1, hi, lo);
            dh[idx] = hi; dl[idx] = lo;
        }
    }
}

// ---------------- 4) tensor-core flash attention (pre-packed operands) ----------
__global__ void __launch_bounds__(128) attn_kernel(const float* __restrict__ bias_table) {
    const int qt = blockIdx.x, h = blockIdx.y, b = blockIdx.z;
    const int tid = threadIdx.x, warp = tid >> 5, lane = tid & 31;
    const int g = lane >> 2, t = lane & 3;
    const int qw0 = qt * 128 + warp * 32;

    __shared__ float    s_bias[BIASN + 3];
    __shared__ uint32_t sK[2][32][17];
    __shared__ uint32_t sV[2][32][17];

    for (int i = tid; i < BIASN; i += 128)
        s_bias[i] = bias_table[i * HEADS + h];

    // Q fragments from d-pair packed words
    uint32_t qf[2][2][2][4];
#pragma unroll
    for (int mt = 0; mt < 2; mt++) {
        const int row0 = qw0 + mt * 16 + g;
#pragma unroll
        for (int kc = 0; kc < 2; kc++) {
            const int cp0 = h * 16 + kc * 8 + t;
#pragma unroll
            for (int sp = 0; sp < 2; sp++) {
                const uint32_t* qp = &g_qkp[0][b][sp][0];
                qf[sp][mt][kc][0] = qp[cp0 * 1024 + row0];
                qf[sp][mt][kc][1] = qp[cp0 * 1024 + row0 + 8];
                qf[sp][mt][kc][2] = qp[(cp0 + 4) * 1024 + row0];
                qf[sp][mt][kc][3] = qp[(cp0 + 4) * 1024 + row0 + 8];
            }
        }
    }

    int yq[2][2], xq[2][2];
#pragma unroll
    for (int mt = 0; mt < 2; mt++)
#pragma unroll
        for (int rh = 0; rh < 2; rh++) {
            int q = qw0 + mt * 16 + g + rh * 8;
            yq[mt][rh] = q >> 5; xq[mt][rh] = q & 31;
        }

    float m[2][2], l[2][2];
    float o[2][4][4];
#pragma unroll
    for (int mt = 0; mt < 2; mt++)
#pragma unroll
        for (int rh = 0; rh < 2; rh++) { m[mt][rh] = -1e30f; l[mt][rh] = 0.f; }
#pragma unroll
    for (int mt = 0; mt < 2; mt++)
#pragma unroll
        for (int n = 0; n < 4; n++)
#pragma unroll
            for (int r = 0; r < 4; r++) o[mt][n][r] = 0.f;

    for (int kt = 0; kt < 32; kt++) {
        const int kv0 = kt * 32;
        __syncthreads();
        // K fill: coalesced copies of d-pair packed words
        for (int e = tid; e < 1024; e += 128) {
            int sp = e >> 9, r = e & 511;
            int kv = r & 31, dp = r >> 5;
            sK[sp][kv][dp] = g_qkp[1][b][sp][(h * 16 + dp) * 1024 + kv0 + kv];
        }
        // V fill: coalesced copies of token-pair packed words
        for (int e = tid; e < 1024; e += 128) {
            int sp = e >> 9, r = e & 511;
            int kvp = r & 15, d = r >> 4;
            sV[sp][d][kvp] = g_vp[b][sp][(h * 32 + d) * 512 + (kv0 >> 1) + kvp];
        }
        __syncthreads();

        float sc[2][4][4];
#pragma unroll
        for (int mt = 0; mt < 2; mt++)
#pragma unroll
            for (int j = 0; j < 4; j++)
#pragma unroll
                for (int r = 0; r < 4; r++) sc[mt][j][r] = 0.f;

#pragma unroll
        for (int kc = 0; kc < 2; kc++) {
            uint32_t kf[2][4][2];
#pragma unroll
            for (int sp = 0; sp < 2; sp++)
#pragma unroll
                for (int j = 0; j < 4; j++) {
                    kf[sp][j][0] = sK[sp][j * 8 + g][kc * 8 + t];
                    kf[sp][j][1] = sK[sp][j * 8 + g][kc * 8 + 4 + t];
                }
#pragma unroll
            for (int mt = 0; mt < 2; mt++)
#pragma unroll
                for (int j = 0; j < 4; j++) {
                    mma16816(sc[mt][j], qf[0][mt][kc], kf[0][j]);
                    mma16816(sc[mt][j], qf[1][mt][kc], kf[0][j]);
                    mma16816(sc[mt][j], qf[0][mt][kc], kf[1][j]);
                }
        }

#pragma unroll
        for (int mt = 0; mt < 2; mt++)
#pragma unroll
            for (int j = 0; j < 4; j++)
#pragma unroll
                for (int r = 0; r < 4; r++) {
                    int kv = kv0 + j * 8 + 2 * t + (r & 1);
                    int rh = r >> 1;
                    int idx = (yq[mt][rh] - (kv >> 5) + 31) * 63 + (xq[mt][rh] - (kv & 31) + 31);
                    sc[mt][j][r] += s_bias[idx];
                }

#pragma unroll
        for (int mt = 0; mt < 2; mt++)
#pragma unroll
            for (int rh = 0; rh < 2; rh++) {
                float tm = sc[mt][0][2 * rh];
#pragma unroll
                for (int j = 0; j < 4; j++) {
                    tm = fmaxf(tm, sc[mt][j][2 * rh]);
                    tm = fmaxf(tm, sc[mt][j][2 * rh + 1]);
                }
                tm = fmaxf(tm, __shfl_xor_sync(0xffffffffu, tm, 1));
                tm = fmaxf(tm, __shfl_xor_sync(0xffffffffu, tm, 2));
                float mo = m[mt][rh];
                float mn = fmaxf(mo, tm);
                float scale = __expf(mo - mn);
                m[mt][rh] = mn;
                l[mt][rh] *= scale;
#pragma unroll
                for (int n = 0; n < 4; n++) {
                    o[mt][n][2 * rh]     *= scale;
                    o[mt][n][2 * rh + 1] *= scale;
                }
            }
#pragma unroll
        for (int mt = 0; mt < 2; mt++)
#pragma unroll
            for (int j = 0; j < 4; j++)
#pragma unroll
                for (int r = 0; r < 4; r++) {
                    float p = __expf(sc[mt][j][r] - m[mt][r >> 1]);
                    sc[mt][j][r] = p;
                    l[mt][r >> 1] += p;
                }

#pragma unroll
        for (int kk = 0; kk < 2; kk++) {
            uint32_t vf[2][4][2];
#pragma unroll
            for (int sp = 0; sp < 2; sp++)
#pragma unroll
                for (int n = 0; n < 4; n++) {
                    vf[sp][n][0] = sV[sp][n * 8 + g][kk * 8 + t];
                    vf[sp][n][1] = sV[sp][n * 8 + g][kk * 8 + 4 + t];
                }
#pragma unroll
            for (int mt = 0; mt < 2; mt++) {
                uint32_t pf[2][4];
                split2(sc[mt][2 * kk][0],     sc[mt][2 * kk][1],     pf[0][0], pf[1][0]);
                split2(sc[mt][2 * kk][2],     sc[mt][2 * kk][3],     pf[0][1], pf[1][1]);
                split2(sc[mt][2 * kk + 1][0], sc[mt][2 * kk + 1][1], pf[0][2], pf[1][2]);
                split2(sc[mt][2 * kk + 1][2], sc[mt][2 * kk + 1][3], pf[0][3], pf[1][3]);
#pragma unroll
                for (int n = 0; n < 4; n++) {
                    mma16816(o[mt][n], pf[0], vf[0][n]);
                    mma16816(o[mt][n], pf[1], vf[0][n]);
                    mma16816(o[mt][n], pf[0], vf[1][n]);
                }
            }
        }
    }

    float linv[2][2];
#pragma unroll
    for (int mt = 0; mt < 2; mt++)
#pragma unroll
        for (int rh = 0; rh < 2; rh++) {
            float ls = l[mt][rh];
            ls += __shfl_xor_sync(0xffffffffu, ls, 1);
            ls += __shfl_xor_sync(0xffffffffu, ls, 2);
            linv[mt][rh] = 1.f / ls;
        }
    float* ao = &g_attn[(b * 256 + h * DHEAD) * NTOK];
#pragma unroll
    for (int mt = 0; mt < 2; mt++)
#pragma unroll
        for (int n = 0; n < 4; n++)
#pragma unroll
            for (int r = 0; r < 4; r++) {
                int q = qw0 + mt * 16 + g + (r >> 1) * 8;
                int d = n * 8 + 2 * t + (r & 1);
                ao[d * NTOK + q] = o[mt][n][r] * linv[mt][r >> 1];
            }
}

// ---------------- 5) 1x1 output projection ----------------
__global__ void outproj_kernel(const float* __restrict__ bo, float* __restrict__ out) {
    const int nt = blockIdx.x;
    const int b  = blockIdx.y;
    const int oc = threadIdx.x;

    __shared__ __align__(16) float s_a[256 * 32];
    for (int e = oc; e < 8192; e += 256) {
        int c = e >> 5, px = e & 31;
        s_a[e] = g_attn[(b * 256 + c) * NTOK + nt * 32 + px];
    }
    __syncthreads();

    ull acc[16];
#pragma unroll
    for (int p = 0; p < 16; p++) acc[p] = 0ull;

    for (int c = 0; c < 256; c++) {
        float wv = g_woT[c * 256 + oc];
        ull w2 = pack2(wv, wv);
        const ulonglong2* arow2 = reinterpret_cast<const ulonglong2*>(&s_a[c * 32]);
#pragma unroll
        for (int p8 = 0; p8 < 8; p8++) {
            ulonglong2 vv = arow2[p8];
            ffma2(acc[2 * p8],     w2, vv.x);
            ffma2(acc[2 * p8 + 1], w2, vv.y);
        }
    }

    const float bb = bo[oc];
    float* op = out + (b * 256 + oc) * NTOK + nt * 32;
#pragma unroll
    for (int p = 0; p < 16; p += 2) {
        float4 v4 = make_float4(lo2(acc[p]) + bb,     hi2(acc[p]) + bb,
                                lo2(acc[p + 1]) + bb, hi2(acc[p + 1]) + bb);
        *reinterpret_cast<float4*>(op + 2 * p) = v4;
    }
}

// ---------------- launch ----------------
extern "C" void kernel_launch(void* const* d_in, const int* in_sizes, int n_in,
                              void* d_out, int out_size) {
    const float* x  = (const float*)d_in[0];
    const float* wq = (const float*)d_in[1];
    const float* wk = (const float*)d_in[2];
    const float* wv = (const float*)d_in[3];
    const float* gq = (const float*)d_in[4];
    const float* bq = (const float*)d_in[5];
    const float* gk = (const float*)d_in[6];
    const float* bk = (const float*)d_in[7];
    const float* gv = (const float*)d_in[8];
    const float* bv = (const float*)d_in[9];
    const float* bt = (const float*)d_in[10];
    const float* wo = (const float*)d_in[11];
    const float* bo = (const float*)d_in[12];
    float* out = (float*)d_out;

    prep_w_kernel<<<dim3(64, 9, 3), 256>>>(wq, wk, wv);
    prep_x_kernel<<<dim3(34, BATCH), 256>>>(x);
    transpose_wo_kernel<<<dim3(8, 8), dim3(32, 8)>>>(wo);
    conv_mma_kernel<<<dim3(16, 3, BATCH), 256>>>();
    gn_gelu_kernel<<<dim3(8, BATCH, 3), 256>>>(gq, bq, gk, bk, gv, bv);
    attn_kernel<<<dim3(8, HEADS, BATCH), 128>>>(bt);
    outproj_kernel<<<dim3(32, BATCH), 256>>>(bo, out);
}

// round 16
// speedup vs baseline: 1.2240x; 1.0508x over previous
#include <cuda_runtime.h>
#include <cuda_bf16.h>
#include <cstdint>
#include <cstring>

typedef unsigned long long ull;

// Problem constants
#define BATCH 8
#define CHAN  256
#define HEADS 8
#define DHEAD 32
#define NTOK  1024
#define NPER  262144
#define BIASN 3969

// ---------------- scratch ----------------
// conv W fragments (ic-permuted): [p][tap][split][kc(16)][npair(16)][lane(32)][2 x 8B]
__device__ __align__(16) __nv_bfloat16 g_wfragB[3*9*2*16*32*32*4];
// X transposed+padded bf16 split: [b][split][y(34)][x(34)][c(256)]
__device__ __align__(16) __nv_bfloat16 g_xbfT[8*2*34*34*256];
// wo fragments (unpermuted): [split][kc(16)][npair(16)][lane(32)][2 x 8B]
__device__ __align__(16) __nv_bfloat16 g_wofrag[2*16*32*32*4];
__device__ __align__(16) float g_act[3][BATCH*NPER];           // conv outputs (pre-GN)
__device__ __align__(16) float g_part[3][BATCH][16][2];        // GN partials
// packed post-GN/GELU activations (bf16x2 words, hi/lo splits)
__device__ __align__(16) uint32_t g_qkp[2][BATCH][2][128*1024]; // Q,K: [cp][n]
__device__ __align__(16) uint32_t g_vp[BATCH][2][256*512];      // V: [c][np]
// packed attention output: [b][split][q(1024)][cp(128)]
__device__ __align__(16) uint32_t g_op[BATCH][2][1024*128];

// ---------------- helpers ----------------
__device__ __forceinline__ void mma16816(float* c, const uint32_t* a, const uint32_t* b) {
    asm volatile("mma.sync.aligned.m16n8k16.row.col.f32.bf16.bf16.f32 "
        "{%0,%1,%2,%3}, {%4,%5,%6,%7}, {%8,%9}, {%0,%1,%2,%3};"
        : "+f"(c[0]), "+f"(c[1]), "+f"(c[2]), "+f"(c[3])
        : "r"(a[0]), "r"(a[1]), "r"(a[2]), "r"(a[3]), "r"(b[0]), "r"(b[1]));
}
__device__ __forceinline__ void split2(float v0, float v1, uint32_t& hi, uint32_t& lo) {
    __nv_bfloat16 h0 = __float2bfloat16(v0), h1 = __float2bfloat16(v1);
    __nv_bfloat16 l0 = __float2bfloat16(v0 - __bfloat162float(h0));
    __nv_bfloat16 l1 = __float2bfloat16(v1 - __bfloat162float(h1));
    __nv_bfloat162 ph; ph.x = h0; ph.y = h1;
    __nv_bfloat162 pl; pl.x = l0; pl.y = l1;
    hi = *reinterpret_cast<uint32_t*>(&ph);
    lo = *reinterpret_cast<uint32_t*>(&pl);
}

// ---------------- 1a) conv weight prep (ic-permuted) ----------------
__global__ void prep_w_kernel(const float* __restrict__ wq,
                              const float* __restrict__ wk,
                              const float* __restrict__ wv) {
    const int sub = threadIdx.x >> 5, lane = threadIdx.x & 31;
    const int fi = blockIdx.x * 8 + sub;
    const int kc = fi >> 5, ntile = fi & 31;
    const int tap = blockIdx.y, p = blockIdx.z;
    const float* w = (p == 0) ? wq : (p == 1) ? wk : wv;
    const int t = lane & 3, g = lane >> 2;
    const int oc = ntile * 8 + g;
    const int k0 = kc * 16 + t * 4;
    const int npair = ntile >> 1, half = ntile & 1;

    float v0 = w[oc * 2304 + (k0    ) * 9 + tap];
    float v1 = w[oc * 2304 + (k0 + 1) * 9 + tap];
    float v2 = w[oc * 2304 + (k0 + 2) * 9 + tap];
    float v3 = w[oc * 2304 + (k0 + 3) * 9 + tap];

    uint32_t hi01, lo01, hi23, lo23;
    split2(v0, v1, hi01, lo01);
    split2(v2, v3, hi23, lo23);

    int slot = (((((p * 9 + tap) * 2 + 0) * 16 + kc) * 16 + npair) * 32 + lane) * 2 + half;
    uint32_t* dh = reinterpret_cast<uint32_t*>(g_wfragB) + slot * 2;
    dh[0] = hi01; dh[1] = hi23;
    uint32_t* dl = dh + 16 * 32 * 32 * 2;
    dl[0] = lo01; dl[1] = lo23;
}

// ---------------- 1b) input transpose + pad + bf16-split ----------------
__global__ void prep_x_kernel(const float* __restrict__ x) {
    const int y = blockIdx.x, b = blockIdx.y, c = threadIdx.x;
    __shared__ float s_t[256][33];
    const bool rowvalid = (y >= 1 && y <= 32);
    if (rowvalid) {
        const float* src = x + ((b * 256 + c) * 32 + (y - 1)) * 32;
#pragma unroll
        for (int i = 0; i < 8; i++) {
            float4 v = reinterpret_cast<const float4*>(src)[i];
            s_t[c][i * 4 + 0] = v.x; s_t[c][i * 4 + 1] = v.y;
            s_t[c][i * 4 + 2] = v.z; s_t[c][i * 4 + 3] = v.w;
        }
    }
    __syncthreads();
    for (int xx = 0; xx < 34; xx++) {
        float v = (rowvalid && xx >= 1 && xx <= 32) ? s_t[c][xx - 1] : 0.f;
        __nv_bfloat16 hi = __float2bfloat16(v);
        __nv_bfloat16 lo = __float2bfloat16(v - __bfloat162float(hi));
        int base = (((b * 2) * 34 + y) * 34 + xx) * 256 + c;
        g_xbfT[base]              = hi;
        g_xbfT[base + 34*34*256]  = lo;
    }
}

// ---------------- 1c) wo fragment prep (UNpermuted k order) ----------------
// grid 64, block 256. Frag b0 = w[oc][{k0,k0+1}], b1 = w[oc][{k0+8,k0+9}], k0=kc*16+2t.
__global__ void prep_wo_kernel(const float* __restrict__ wo) {
    const int sub = threadIdx.x >> 5, lane = threadIdx.x & 31;
    const int fi = blockIdx.x * 8 + sub;
    const int kc = fi >> 5, ntile = fi & 31;
    const int t = lane & 3, g = lane >> 2;
    const int oc = ntile * 8 + g;
    const int k0 = kc * 16 + 2 * t;
    const int npair = ntile >> 1, half = ntile & 1;

    float v0 = wo[oc * 256 + k0];
    float v1 = wo[oc * 256 + k0 + 1];
    float v2 = wo[oc * 256 + k0 + 8];
    float v3 = wo[oc * 256 + k0 + 9];

    uint32_t hi01, lo01, hi23, lo23;
    split2(v0, v1, hi01, lo01);
    split2(v2, v3, hi23, lo23);

    int slot = ((kc * 16 + npair) * 32 + lane) * 2 + half;
    uint32_t* dh = reinterpret_cast<uint32_t*>(g_wofrag) + slot * 2;
    dh[0] = hi01; dh[1] = hi23;
    uint32_t* dl = dh + 16 * 16 * 32 * 2 * 2;   // sp stride in u32
    dl[0] = lo01; dl[1] = lo23;
}

// ---------------- conv fragment load helpers ----------------
__device__ __forceinline__ void load_afrag(uint32_t afr[2][2][4],
                                           const __nv_bfloat16* const abase[2][2],
                                           int kofs) {
#pragma unroll
    for (int mt = 0; mt < 2; mt++)
#pragma unroll
        for (int sp = 0; sp < 2; sp++) {
            const __nv_bfloat16* xp = abase[mt][sp] + kofs;
            ull v0 = *reinterpret_cast<const ull*>(xp);
            ull v1 = *reinterpret_cast<const ull*>(xp + 2048);
            afr[sp][mt][0] = (uint32_t)v0;
            afr[sp][mt][2] = (uint32_t)(v0 >> 32);
            afr[sp][mt][1] = (uint32_t)v1;
            afr[sp][mt][3] = (uint32_t)(v1 >> 32);
        }
}
__device__ __forceinline__ void load_bfrag(uint32_t bfr[2][8][2],
                                           const uint4* const bbase[2],
                                           int kofs) {
#pragma unroll
    for (int sp = 0; sp < 2; sp++) {
        const uint4* wb = bbase[sp] + kofs;
#pragma unroll
        for (int n4 = 0; n4 < 4; n4++) {
            uint4 v = wb[n4 * 32];
            bfr[sp][2 * n4][0]     = v.x;
            bfr[sp][2 * n4][1]     = v.y;
            bfr[sp][2 * n4 + 1][0] = v.z;
            bfr[sp][2 * n4 + 1][1] = v.w;
        }
    }
}

// ---------------- 2) conv via mma.sync, kc-pipelined (exact R14 mainloop) ----------
__global__ void __launch_bounds__(256) conv_mma_kernel() {
    const int nt  = blockIdx.x;
    const int p   = blockIdx.y;
    const int b   = blockIdx.z;
    const int tid = threadIdx.x, warp = tid >> 5, lane = tid & 31;
    const int wm = warp & 1, wn = warp >> 1;
    const int g = lane >> 2, t = lane & 3;
    const int px_warp = nt * 64 + wm * 32;

    float acc[2][8][4];
#pragma unroll
    for (int mt = 0; mt < 2; mt++)
#pragma unroll
        for (int n8 = 0; n8 < 8; n8++)
#pragma unroll
            for (int r = 0; r < 4; r++) acc[mt][n8][r] = 0.f;

    uint32_t afr[2][2][2][4];
    uint32_t bfr[2][2][8][2];

    for (int tap = 0; tap < 9; tap++) {
        const int ky = tap / 3, kx = tap - ky * 3;

        const __nv_bfloat16* abase[2][2];
#pragma unroll
        for (int mt = 0; mt < 2; mt++) {
            const int px = px_warp + mt * 16 + g;
            const int y  = (px >> 5) + ky;
            const int x  = (px & 31) + kx;
#pragma unroll
            for (int sp = 0; sp < 2; sp++)
                abase[mt][sp] = g_xbfT + (((b * 2 + sp) * 34 + y) * 34 + x) * 256 + t * 4;
        }
        const uint4* bbase[2];
#pragma unroll
        for (int sp = 0; sp < 2; sp++)
            bbase[sp] = reinterpret_cast<const uint4*>(g_wfragB) +
                ((((p * 9 + tap) * 2 + sp) * 16) * 16 + wn * 4) * 32 + lane;

        load_afrag(afr[0], abase, 0);
        load_bfrag(bfr[0], bbase, 0);

#pragma unroll 2
        for (int kc = 0; kc < 16; kc++) {
            const int cur = kc & 1, nxt = cur ^ 1;
            if (kc < 15) {
                load_afrag(afr[nxt], abase, (kc + 1) * 16);
                load_bfrag(bfr[nxt], bbase, (kc + 1) * 512);
            }
#pragma unroll
            for (int combo = 0; combo < 3; combo++) {
                const int ws = combo >> 1, xs = combo & 1;
#pragma unroll
                for (int mt = 0; mt < 2; mt++)
#pragma unroll
                    for (int n8 = 0; n8 < 8; n8++)
                        mma16816(acc[mt][n8], afr[cur][xs][mt], bfr[cur][ws][n8]);
            }
        }
    }

    float s = 0.f, sq = 0.f;
#pragma unroll
    for (int mt = 0; mt < 2; mt++)
#pragma unroll
        for (int n8 = 0; n8 < 8; n8++)
#pragma unroll
            for (int r = 0; r < 4; r++) {
                float v  = acc[mt][n8][r];
                int   px = px_warp + mt * 16 + g + ((r >> 1) << 3);
                int   oc = wn * 64 + n8 * 8 + t * 2 + (r & 1);
                g_act[p][(b * 256 + oc) * 1024 + px] = v;
                s += v; sq += v * v;
            }
    __shared__ float red[512];
    red[tid] = s; red[tid + 256] = sq;
    __syncthreads();
    for (int st = 128; st > 0; st >>= 1) {
        if (tid < st) { red[tid] += red[tid + st]; red[tid + 256] += red[tid + 256 + st]; }
        __syncthreads();
    }
    if (tid == 0) {
        g_part[p][b][nt][0] = red[0];
        g_part[p][b][nt][1] = red[256];
    }
}

// ---------------- 3) GroupNorm + GELU + bf16-split packing ----------------
__global__ void gn_gelu_kernel(const float* __restrict__ gq, const float* __restrict__ bq,
                               const float* __restrict__ gk, const float* __restrict__ bk,
                               const float* __restrict__ gv, const float* __restrict__ bv) {
    const int chunk = blockIdx.x;
    const int b     = blockIdx.y;
    const int p     = blockIdx.z;
    const float* gg = (p == 0) ? gq : (p == 1) ? gk : gv;
    const float* bb = (p == 0) ? bq : (p == 1) ? bk : bv;

    __shared__ float s_mu, s_rs;
    if (threadIdx.x < 16) {
        float s  = g_part[p][b][threadIdx.x][0];
        float sq = g_part[p][b][threadIdx.x][1];
#pragma unroll
        for (int o = 8; o > 0; o >>= 1) {
            s  += __shfl_down_sync(0x0000ffffu, s,  o);
            sq += __shfl_down_sync(0x0000ffffu, sq, o);
        }
        if (threadIdx.x == 0) {
            float mu  = s / (float)NPER;
            float var = sq / (float)NPER - mu * mu;
            s_mu = mu;
            s_rs = rsqrtf(var + 1e-6f);
        }
    }
    __syncthreads();
    const float mu = s_mu, rs = s_rs;
    const float* act = &g_act[p][b * NPER];

    if (p < 2) {
        uint32_t* dh = &g_qkp[p][b][0][0];
        uint32_t* dl = &g_qkp[p][b][1][0];
        for (int i = threadIdx.x; i < 16384; i += 256) {
            int idx = chunk * 16384 + i;
            int cp = idx >> 10, n = idx & 1023;
            float v0 = act[(2 * cp) * 1024 + n];
            float v1 = act[(2 * cp + 1) * 1024 + n];
            float gc0 = gg[2 * cp], bc0 = bb[2 * cp];
            float gc1 = gg[2 * cp + 1], bc1 = bb[2 * cp + 1];
            float t0 = (v0 - mu) * rs * gc0 + bc0;
            float t1 = (v1 - mu) * rs * gc1 + bc1;
            t0 = 0.5f * t0 * (1.0f + erff(t0 * 0.70710678118654752f));
            t1 = 0.5f * t1 * (1.0f + erff(t1 * 0.70710678118654752f));
            uint32_t hi, lo;
            split2(t0, t1, hi, lo);
            dh[idx] = hi; dl[idx] = lo;
        }
    } else {
        uint32_t* dh = &g_vp[b][0][0];
        uint32_t* dl = &g_vp[b][1][0];
        for (int i = threadIdx.x; i < 16384; i += 256) {
            int idx = chunk * 16384 + i;
            int c = idx >> 9, np = idx & 511;
            float2 vv = *reinterpret_cast<const float2*>(&act[c * 1024 + 2 * np]);
            float gc = gg[c], bc = bb[c];
            float t0 = (vv.x - mu) * rs * gc + bc;
            float t1 = (vv.y - mu) * rs * gc + bc;
            t0 = 0.5f * t0 * (1.0f + erff(t0 * 0.70710678118654752f));
            t1 = 0.5f * t1 * (1.0f + erff(t1 * 0.70710678118654752f));
            uint32_t hi, lo;
            split2(t0, t1, hi, lo);
            dh[idx] = hi; dl[idx] = lo;
        }
    }
}

// ---------------- 4) tensor-core flash attention -> packed output ----------------
__global__ void __launch_bounds__(128) attn_kernel(const float* __restrict__ bias_table) {
    const int qt = blockIdx.x, h = blockIdx.y, b = blockIdx.z;
    const int tid = threadIdx.x, warp = tid >> 5, lane = tid & 31;
    const int g = lane >> 2, t = lane & 3;
    const int qw0 = qt * 128 + warp * 32;

    __shared__ float    s_bias[BIASN + 3];
    __shared__ uint32_t sK[2][32][17];
    __shared__ uint32_t sV[2][32][17];

    for (int i = tid; i < BIASN; i += 128)
        s_bias[i] = bias_table[i * HEADS + h];

    uint32_t qf[2][2][2][4];
#pragma unroll
    for (int mt = 0; mt < 2; mt++) {
        const int row0 = qw0 + mt * 16 + g;
#pragma unroll
        for (int kc = 0; kc < 2; kc++) {
            const int cp0 = h * 16 + kc * 8 + t;
#pragma unroll
            for (int sp = 0; sp < 2; sp++) {
                const uint32_t* qp = &g_qkp[0][b][sp][0];
                qf[sp][mt][kc][0] = qp[cp0 * 1024 + row0];
                qf[sp][mt][kc][1] = qp[cp0 * 1024 + row0 + 8];
                qf[sp][mt][kc][2] = qp[(cp0 + 4) * 1024 + row0];
                qf[sp][mt][kc][3] = qp[(cp0 + 4) * 1024 + row0 + 8];
            }
        }
    }

    int yq[2][2], xq[2][2];
#pragma unroll
    for (int mt = 0; mt < 2; mt++)
#pragma unroll
        for (int rh = 0; rh < 2; rh++) {
            int q = qw0 + mt * 16 + g + rh * 8;
            yq[mt][rh] = q >> 5; xq[mt][rh] = q & 31;
        }

    float m[2][2], l[2][2];
    float o[2][4][4];
#pragma unroll
    for (int mt = 0; mt < 2; mt++)
#pragma unroll
        for (int rh = 0; rh < 2; rh++) { m[mt][rh] = -1e30f; l[mt][rh] = 0.f; }
#pragma unroll
    for (int mt = 0; mt < 2; mt++)
#pragma unroll
        for (int n = 0; n < 4; n++)
#pragma unroll
            for (int r = 0; r < 4; r++) o[mt][n][r] = 0.f;

    for (int kt = 0; kt < 32; kt++) {
        const int kv0 = kt * 32;
        __syncthreads();
        for (int e = tid; e < 1024; e += 128) {
            int sp = e >> 9, r = e & 511;
            int kv = r & 31, dp = r >> 5;
            sK[sp][kv][dp] = g_qkp[1][b][sp][(h * 16 + dp) * 1024 + kv0 + kv];
        }
        for (int e = tid; e < 1024; e += 128) {
            int sp = e >> 9, r = e & 511;
            int kvp = r & 15, d = r >> 4;
            sV[sp][d][kvp] = g_vp[b][sp][(h * 32 + d) * 512 + (kv0 >> 1) + kvp];
        }
        __syncthreads();

        float sc[2][4][4];
#pragma unroll
        for (int mt = 0; mt < 2; mt++)
#pragma unroll
            for (int j = 0; j < 4; j++)
#pragma unroll
                for (int r = 0; r < 4; r++) sc[mt][j][r] = 0.f;

#pragma unroll
        for (int kc = 0; kc < 2; kc++) {
            uint32_t kf[2][4][2];
#pragma unroll
            for (int sp = 0; sp < 2; sp++)
#pragma unroll
                for (int j = 0; j < 4; j++) {
                    kf[sp][j][0] = sK[sp][j * 8 + g][kc * 8 + t];
                    kf[sp][j][1] = sK[sp][j * 8 + g][kc * 8 + 4 + t];
                }
#pragma unroll
            for (int mt = 0; mt < 2; mt++)
#pragma unroll
                for (int j = 0; j < 4; j++) {
                    mma16816(sc[mt][j], qf[0][mt][kc], kf[0][j]);
                    mma16816(sc[mt][j], qf[1][mt][kc], kf[0][j]);
                    mma16816(sc[mt][j], qf[0][mt][kc], kf[1][j]);
                }
        }

#pragma unroll
        for (int mt = 0; mt < 2; mt++)
#pragma unroll
            for (int j = 0; j < 4; j++)
#pragma unroll
                for (int r = 0; r < 4; r++) {
                    int kv = kv0 + j * 8 + 2 * t + (r & 1);
                    int rh = r >> 1;
                    int idx = (yq[mt][rh] - (kv >> 5) + 31) * 63 + (xq[mt][rh] - (kv & 31) + 31);
                    sc[mt][j][r] += s_bias[idx];
                }

#pragma unroll
        for (int mt = 0; mt < 2; mt++)
#pragma unroll
            for (int rh = 0; rh < 2; rh++) {
                float tm = sc[mt][0][2 * rh];
#pragma unroll
                for (int j = 0; j < 4; j++) {
                    tm = fmaxf(tm, sc[mt][j][2 * rh]);
                    tm = fmaxf(tm, sc[mt][j][2 * rh + 1]);
                }
                tm = fmaxf(tm, __shfl_xor_sync(0xffffffffu, tm, 1));
                tm = fmaxf(tm, __shfl_xor_sync(0xffffffffu, tm, 2));
                float mo = m[mt][rh];
                float mn = fmaxf(mo, tm);
                float scale = __expf(mo - mn);
                m[mt][rh] = mn;
                l[mt][rh] *= scale;
#pragma unroll
                for (int n = 0; n < 4; n++) {
                    o[mt][n][2 * rh]     *= scale;
                    o[mt][n][2 * rh + 1] *= scale;
                }
            }
#pragma unroll
        for (int mt = 0; mt < 2; mt++)
#pragma unroll
            for (int j = 0; j < 4; j++)
#pragma unroll
                for (int r = 0; r < 4; r++) {
                    float p = __expf(sc[mt][j][r] - m[mt][r >> 1]);
                    sc[mt][j][r] = p;
                    l[mt][r >> 1] += p;
                }

#pragma unroll
        for (int kk = 0; kk < 2; kk++) {
            uint32_t vf[2][4][2];
#pragma unroll
            for (int sp = 0; sp < 2; sp++)
#pragma unroll
                for (int n = 0; n < 4; n++) {
                    vf[sp][n][0] = sV[sp][n * 8 + g][kk * 8 + t];
                    vf[sp][n][1] = sV[sp][n * 8 + g][kk * 8 + 4 + t];
                }
#pragma unroll
            for (int mt = 0; mt < 2; mt++) {
                uint32_t pf[2][4];
                split2(sc[mt][2 * kk][0],     sc[mt][2 * kk][1],     pf[0][0], pf[1][0]);
                split2(sc[mt][2 * kk][2],     sc[mt][2 * kk][3],     pf[0][1], pf[1][1]);
                split2(sc[mt][2 * kk + 1][0], sc[mt][2 * kk + 1][1], pf[0][2], pf[1][2]);
                split2(sc[mt][2 * kk + 1][2], sc[mt][2 * kk + 1][3], pf[0][3], pf[1][3]);
#pragma unroll
                for (int n = 0; n < 4; n++) {
                    mma16816(o[mt][n], pf[0], vf[0][n]);
                    mma16816(o[mt][n], pf[1], vf[0][n]);
                    mma16816(o[mt][n], pf[0], vf[1][n]);
                }
            }
        }
    }

    float linv[2][2];
#pragma unroll
    for (int mt = 0; mt < 2; mt++)
#pragma unroll
        for (int rh = 0; rh < 2; rh++) {
            float ls = l[mt][rh];
            ls += __shfl_xor_sync(0xffffffffu, ls, 1);
            ls += __shfl_xor_sync(0xffffffffu, ls, 2);
            linv[mt][rh] = 1.f / ls;
        }
    // epilogue: split-pack adjacent-d pairs -> g_op[b][sp][q][cp]
    uint32_t* oph = &g_op[b][0][0];
    uint32_t* opl = &g_op[b][1][0];
#pragma unroll
    for (int mt = 0; mt < 2; mt++)
#pragma unroll
        for (int n = 0; n < 4; n++)
#pragma unroll
            for (int rh = 0; rh < 2; rh++) {
                int q  = qw0 + mt * 16 + g + rh * 8;
                int cp = h * 16 + n * 4 + t;
                uint32_t hi, lo;
                split2(o[mt][n][2 * rh] * linv[mt][rh],
                       o[mt][n][2 * rh + 1] * linv[mt][rh], hi, lo);
                oph[q * 128 + cp] = hi;
                opl[q * 128 + cp] = lo;
            }
}

// ---------------- 5) output projection via mma.sync ----------------
// grid (16 ntiles, 8 b), block 256 (8 warps = 2m x 4n); K = 256 (16 kc)
__global__ void __launch_bounds__(256) outproj_mma_kernel(const float* __restrict__ bo,
                                                          float* __restrict__ out) {
    const int nt = blockIdx.x, b = blockIdx.y;
    const int tid = threadIdx.x, warp = tid >> 5, lane = tid & 31;
    const int wm = warp & 1, wn = warp >> 1;
    const int g = lane >> 2, t = lane & 3;
    const int px_warp = nt * 64 + wm * 32;

    float acc[2][8][4];
#pragma unroll
    for (int mt = 0; mt < 2; mt++)
#pragma unroll
        for (int n8 = 0; n8 < 8; n8++)
#pragma unroll
            for (int r = 0; r < 4; r++) acc[mt][n8][r] = 0.f;

    for (int kc = 0; kc < 16; kc++) {
        uint32_t afr[2][2][4];
#pragma unroll
        for (int mt = 0; mt < 2; mt++) {
            const int row0 = px_warp + mt * 16 + g;
#pragma unroll
            for (int sp = 0; sp < 2; sp++) {
                const uint32_t* ap = &g_op[b][sp][0];
                afr[sp][mt][0] = ap[row0 * 128 + kc * 8 + t];
                afr[sp][mt][1] = ap[(row0 + 8) * 128 + kc * 8 + t];
                afr[sp][mt][2] = ap[row0 * 128 + kc * 8 + 4 + t];
                afr[sp][mt][3] = ap[(row0 + 8) * 128 + kc * 8 + 4 + t];
            }
        }
        uint32_t bfr[2][8][2];
#pragma unroll
        for (int sp = 0; sp < 2; sp++) {
            const uint4* wb = reinterpret_cast<const uint4*>(g_wofrag) +
                ((sp * 16 + kc) * 16 + wn * 4) * 32 + lane;
#pragma unroll
            for (int n4 = 0; n4 < 4; n4++) {
                uint4 v = wb[n4 * 32];
                bfr[sp][2 * n4][0]     = v.x;
                bfr[sp][2 * n4][1]     = v.y;
                bfr[sp][2 * n4 + 1][0] = v.z;
                bfr[sp][2 * n4 + 1][1] = v.w;
            }
        }
#pragma unroll
        for (int combo = 0; combo < 3; combo++) {
            const int ws = combo >> 1, xs = combo & 1;
#pragma unroll
            for (int mt = 0; mt < 2; mt++)
#pragma unroll
                for (int n8 = 0; n8 < 8; n8++)
                    mma16816(acc[mt][n8], afr[xs][mt], bfr[ws][n8]);
        }
    }

#pragma unroll
    for (int mt = 0; mt < 2; mt++)
#pragma unroll
        for (int n8 = 0; n8 < 8; n8++)
#pragma unroll
            for (int r = 0; r < 4; r++) {
                int q  = px_warp + mt * 16 + g + ((r >> 1) << 3);
                int oc = wn * 64 + n8 * 8 + 2 * t + (r & 1);
                out[(b * 256 + oc) * 1024 + q] = acc[mt][n8][r] + bo[oc];
            }
}

// ---------------- launch ----------------
extern "C" void kernel_launch(void* const* d_in, const int* in_sizes, int n_in,
                              void* d_out, int out_size) {
    const float* x  = (const float*)d_in[0];
    const float* wq = (const float*)d_in[1];
    const float* wk = (const float*)d_in[2];
    const float* wv = (const float*)d_in[3];
    const float* gq = (const float*)d_in[4];
    const float* bq = (const float*)d_in[5];
    const float* gk = (const float*)d_in[6];
    const float* bk = (const float*)d_in[7];
    const float* gv = (const float*)d_in[8];
    const float* bv = (const float*)d_in[9];
    const float* bt = (const float*)d_in[10];
    const float* wo = (const float*)d_in[11];
    const float* bo = (const float*)d_in[12];
    float* out = (float*)d_out;

    prep_w_kernel<<<dim3(64, 9, 3), 256>>>(wq, wk, wv);
    prep_x_kernel<<<dim3(34, BATCH), 256>>>(x);
    prep_wo_kernel<<<64, 256>>>(wo);
    conv_mma_kernel<<<dim3(16, 3, BATCH), 256>>>();
    gn_gelu_kernel<<<dim3(8, BATCH, 3), 256>>>(gq, bq, gk, bk, gv, bv);
    attn_kernel<<<dim3(8, HEADS, BATCH), 128>>>(bt);
    outproj_mma_kernel<<<dim3(16, BATCH), 256>>>(bo, out);
}